// round 2
// baseline (speedup 1.0000x reference)
#include <cuda_runtime.h>
#include <math.h>

#define NLEV 5
#define NPIX 35464
#define NANCH 106392
#define PRE_NMS 6000
#define POST_NMS 1000
#define NMS_TH 0.7f
#define CAND_MAX 16384
#define NWORDS 94   // ceil(6000/64)

// ---------------- device scratch (static, no allocs) ----------------
__device__ float g_f[(size_t)NPIX * 512];          // hidden features, 72.6MB
__device__ float g_wT[2304 * 512];                  // repacked conv weights [tap*256+ic][oc]
__device__ float g_scores[NANCH];
__device__ unsigned g_keys[NANCH];
__device__ float g_deltas[(size_t)NANCH * 4];
__device__ unsigned g_hist[256];
__device__ unsigned g_prefix;
__device__ int g_remaining;
__device__ int g_candCount;
__device__ unsigned long long g_cand[CAND_MAX];
__device__ int g_selIdx[PRE_NMS];
__device__ float g_selScore[PRE_NMS];
__device__ float g_boxes[PRE_NMS * 4];
__device__ unsigned long long g_iou[(size_t)PRE_NMS * NWORDS];
__device__ int g_keep[POST_NMS];
__device__ int g_numKeep;

// anchor constants
__constant__ int c_aoff[6] = {0, 79872, 99840, 104832, 106080, 106392};
__constant__ int c_W[5] = {208, 104, 52, 26, 13};
__constant__ int c_stride[5] = {4, 8, 16, 32, 64};
// np.round(sqrt(b^2/r)) and np.round(ws*r) with half-to-even, per (level, ratio)
__constant__ int c_ws0[15] = {6,4,3, 11,8,6, 23,16,11, 45,32,23, 91,64,45};
__constant__ int c_hs0[15] = {3,4,6, 6,8,12, 12,16,22, 22,32,46, 46,64,90};

// ---------------- weight repack: [oc][ic][3][3] -> [tap*256+ic][oc] ----------------
__global__ void repack_kernel(const float* __restrict__ w) {
    for (int t = blockIdx.x * blockDim.x + threadIdx.x; t < 2304 * 512;
         t += gridDim.x * blockDim.x) {
        int k = t >> 9, oc = t & 511;
        int tap = k >> 8, ic = k & 255;
        g_wT[t] = w[oc * 2304 + ic * 9 + tap];
    }
}

// ---------------- 3x3 conv as implicit GEMM: tile 128 pix x 64 oc, BK=16 ----------------
__global__ __launch_bounds__(256) void conv3x3_kernel(
    const float* __restrict__ in, const float* __restrict__ bias,
    int H, int W, int pixBase)
{
    const int HW = H * W;
    __shared__ float As[16][132];
    __shared__ float Bs[16][64];
    int tid = threadIdx.x;
    int pix0 = blockIdx.y * 128;
    int oc0 = blockIdx.z * 64;

    int lcol = tid & 127, lrow = tid >> 7;      // A loader: col = pixel, 2 rows/pass
    int myPix = pix0 + lcol;
    int py = myPix / W, px = myPix - py * W;
    bool pValid = myPix < HW;

    int bcol = tid & 63, brow = tid >> 6;        // B loader

    int ty = tid >> 4, tx = tid & 15;            // compute: 8 pix x 4 oc per thread
    float acc[8][4];
#pragma unroll
    for (int j = 0; j < 8; j++)
#pragma unroll
        for (int i = 0; i < 4; i++) acc[j][i] = 0.f;

    for (int k0 = 0; k0 < 2304; k0 += 16) {
        int tap = k0 >> 8;
        int ic0 = k0 & 255;
        int dy = tap / 3 - 1;
        int dx = tap - (tap / 3) * 3 - 1;
        int iy = py + dy, ix = px + dx;
        bool v = pValid && ((unsigned)iy < (unsigned)H) && ((unsigned)ix < (unsigned)W);
        const float* src = in + (long long)iy * W + ix;
#pragma unroll
        for (int i = 0; i < 8; i++) {
            int kk = lrow + i * 2;
            As[kk][lcol] = v ? __ldg(src + (long long)(ic0 + kk) * HW) : 0.f;
        }
#pragma unroll
        for (int i = 0; i < 4; i++) {
            int kk = brow + i * 4;
            Bs[kk][bcol] = g_wT[(k0 + kk) * 512 + oc0 + bcol];
        }
        __syncthreads();
#pragma unroll
        for (int kk = 0; kk < 16; kk++) {
            float a[8], b[4];
#pragma unroll
            for (int j = 0; j < 8; j++) a[j] = As[kk][ty * 8 + j];
#pragma unroll
            for (int i = 0; i < 4; i++) b[i] = Bs[kk][tx * 4 + i];
#pragma unroll
            for (int j = 0; j < 8; j++)
#pragma unroll
                for (int i = 0; i < 4; i++) acc[j][i] += a[j] * b[i];
        }
        __syncthreads();
    }
#pragma unroll
    for (int j = 0; j < 8; j++) {
        int pix = pix0 + ty * 8 + j;
        if (pix < HW) {
            float* o = g_f + (size_t)(pixBase + pix) * 512 + oc0 + tx * 4;
#pragma unroll
            for (int i = 0; i < 4; i++) o[i] = acc[j][i] + bias[oc0 + tx * 4 + i];
        }
    }
}

// ---------------- 1x1 heads + softmax: one warp per pixel ----------------
__global__ void heads_kernel(const float* __restrict__ sw, const float* __restrict__ sb,
                             const float* __restrict__ bw, const float* __restrict__ bb)
{
    int gw = (blockIdx.x * blockDim.x + threadIdx.x) >> 5;
    int lane = threadIdx.x & 31;
    if (gw >= NPIX) return;
    const float* f = g_f + (size_t)gw * 512;
    float4 v[4];
#pragma unroll
    for (int j = 0; j < 4; j++)
        v[j] = *(const float4*)(f + j * 128 + lane * 4);

    float c[6];
#pragma unroll
    for (int ch = 0; ch < 6; ch++) {
        const float* w = sw + ch * 512;
        float s = 0.f;
#pragma unroll
        for (int j = 0; j < 4; j++) {
            float4 ww = *(const float4*)(w + j * 128 + lane * 4);
            s += v[j].x * ww.x + v[j].y * ww.y + v[j].z * ww.z + v[j].w * ww.w;
        }
#pragma unroll
        for (int off = 16; off; off >>= 1) s += __shfl_xor_sync(0xffffffffu, s, off);
        c[ch] = s + sb[ch];
    }
    float d[12];
#pragma unroll
    for (int ch = 0; ch < 12; ch++) {
        const float* w = bw + ch * 512;
        float s = 0.f;
#pragma unroll
        for (int j = 0; j < 4; j++) {
            float4 ww = *(const float4*)(w + j * 128 + lane * 4);
            s += v[j].x * ww.x + v[j].y * ww.y + v[j].z * ww.z + v[j].w * ww.w;
        }
#pragma unroll
        for (int off = 16; off; off >>= 1) s += __shfl_xor_sync(0xffffffffu, s, off);
        d[ch] = s + bb[ch];
    }
    int base = gw * 3;
    if (lane < 3) {
        // softmax over {c[a], c[3+a]} -> fg prob == sigmoid(c[3+a]-c[a])
        float s = 1.f / (1.f + expf(c[lane] - c[3 + lane]));
        g_scores[base + lane] = s;
        unsigned bits = __float_as_uint(s);
        unsigned key = bits ^ ((unsigned)((int)bits >> 31) | 0x80000000u);
        g_keys[base + lane] = key;
    }
    if (lane < 12) {
        // delta[(base+a)][cc] with channel = a*4+cc  ->  flat base*4 + lane
        g_deltas[(size_t)base * 4 + lane] = d[lane];
    }
}

// ---------------- radix top-k threshold selection ----------------
__global__ void reset_kernel() {
    int t = threadIdx.x;
    if (t < 256) g_hist[t] = 0;
    if (t == 0) {
        g_prefix = 0; g_remaining = PRE_NMS; g_candCount = 0; g_numKeep = 0;
    }
}

__global__ void hist_kernel(int shift) {
    __shared__ unsigned sh[256];
    if (threadIdx.x < 256) sh[threadIdx.x] = 0;
    __syncthreads();
    unsigned pfx = g_prefix;
    for (int i = blockIdx.x * blockDim.x + threadIdx.x; i < NANCH;
         i += gridDim.x * blockDim.x) {
        unsigned k = g_keys[i];
        bool ok = (shift == 24) || ((k >> (shift + 8)) == (pfx >> (shift + 8)));
        if (ok) atomicAdd(&sh[(k >> shift) & 255u], 1u);
    }
    __syncthreads();
    if (threadIdx.x < 256 && sh[threadIdx.x])
        atomicAdd(&g_hist[threadIdx.x], sh[threadIdx.x]);
}

__global__ void select_kernel(int shift) {
    if (threadIdx.x == 0) {
        int rem = g_remaining;
        unsigned cum = 0;
        for (int b = 255; b >= 0; b--) {
            unsigned h = g_hist[b];
            if (cum + h >= (unsigned)rem) {
                g_prefix |= ((unsigned)b) << shift;
                g_remaining = rem - (int)cum;
                break;
            }
            cum += h;
        }
    }
    __syncthreads();
    if (threadIdx.x < 256) g_hist[threadIdx.x] = 0;
}

__global__ void compact_kernel() {
    unsigned T = g_prefix;
    for (int i = blockIdx.x * blockDim.x + threadIdx.x; i < NANCH;
         i += gridDim.x * blockDim.x) {
        unsigned k = g_keys[i];
        if (k >= T) {
            int p = atomicAdd(&g_candCount, 1);
            if (p < CAND_MAX)
                g_cand[p] = ((unsigned long long)k << 32) | (unsigned)(~i);
        }
    }
}

// ---------------- bitonic sort of candidates (key desc, idx asc) ----------------
__global__ void sort_kernel() {
    extern __shared__ unsigned long long s[];
    int tid = threadIdx.x;
    int cnt = g_candCount;
    if (cnt > CAND_MAX) cnt = CAND_MAX;
    for (int i = tid; i < CAND_MAX; i += blockDim.x)
        s[i] = (i < cnt) ? g_cand[i] : 0ULL;
    __syncthreads();
    for (int k = 2; k <= CAND_MAX; k <<= 1) {
        for (int j = k >> 1; j > 0; j >>= 1) {
            for (int i = tid; i < CAND_MAX; i += blockDim.x) {
                int ixj = i ^ j;
                if (ixj > i) {
                    unsigned long long a = s[i], b = s[ixj];
                    bool desc = ((i & k) == 0);
                    if (desc ? (a < b) : (a > b)) { s[i] = b; s[ixj] = a; }
                }
            }
            __syncthreads();
        }
    }
    for (int i = tid; i < PRE_NMS; i += blockDim.x) {
        unsigned long long e = s[i];
        unsigned idx = ~(unsigned)(e & 0xffffffffu);
        unsigned key = (unsigned)(e >> 32);
        unsigned bits = (key & 0x80000000u) ? (key ^ 0x80000000u) : ~key;
        g_selIdx[i] = (int)idx;
        g_selScore[i] = __uint_as_float(bits);
    }
}

// ---------------- decode + clip only selected 6000 ----------------
__global__ void decode_kernel(const float* __restrict__ im_info) {
    int i = blockIdx.x * blockDim.x + threadIdx.x;
    if (i >= PRE_NMS) return;
    int idx = g_selIdx[i];
    int l = 0;
    while (l < 4 && idx >= c_aoff[l + 1]) l++;
    int local = idx - c_aoff[l];
    int p = local / 3, a = local - p * 3;
    int W = c_W[l];
    int y = p / W, x = p - y * W;
    float stride = (float)c_stride[l];
    float cb = (stride - 1.f) * 0.5f;
    float ws = c_ws0[l * 3 + a] * 8.f, hs = c_hs0[l * 3 + a] * 8.f;
    float sx = x * stride, sy = y * stride;
    float ax1 = sx + cb - 0.5f * (ws - 1.f);
    float ay1 = sy + cb - 0.5f * (hs - 1.f);
    float ax2 = sx + cb + 0.5f * (ws - 1.f);
    float ay2 = sy + cb + 0.5f * (hs - 1.f);
    float w = ax2 - ax1 + 1.f, h = ay2 - ay1 + 1.f;
    float cx = ax1 + 0.5f * w, cy = ay1 + 0.5f * h;
    const float* dd = g_deltas + (size_t)idx * 4;
    float pcx = dd[0] * w + cx;
    float pcy = dd[1] * h + cy;
    float pw = expf(dd[2]) * w;
    float ph = expf(dd[3]) * h;
    float imW = im_info[1] - 1.f, imH = im_info[0] - 1.f;
    g_boxes[i * 4 + 0] = fminf(fmaxf(pcx - 0.5f * pw, 0.f), imW);
    g_boxes[i * 4 + 1] = fminf(fmaxf(pcy - 0.5f * ph, 0.f), imH);
    g_boxes[i * 4 + 2] = fminf(fmaxf(pcx + 0.5f * pw, 0.f), imW);
    g_boxes[i * 4 + 3] = fminf(fmaxf(pcy + 0.5f * ph, 0.f), imH);
}

// ---------------- IoU suppression bitmask ----------------
__global__ void iou_kernel() {
    int t = blockIdx.x * blockDim.x + threadIdx.x;
    if (t >= PRE_NMS * NWORDS) return;
    int i = t / NWORDS, wb = t - i * NWORDS;
    float bx1 = g_boxes[i * 4], by1 = g_boxes[i * 4 + 1];
    float bx2 = g_boxes[i * 4 + 2], by2 = g_boxes[i * 4 + 3];
    float areaI = (bx2 - bx1 + 1.f) * (by2 - by1 + 1.f);
    unsigned long long m = 0;
    int j0 = wb * 64;
    int jend = PRE_NMS - j0; if (jend > 64) jend = 64;
    for (int jj = 0; jj < jend; jj++) {
        int j = j0 + jj;
        float x1 = g_boxes[j * 4], y1 = g_boxes[j * 4 + 1];
        float x2 = g_boxes[j * 4 + 2], y2 = g_boxes[j * 4 + 3];
        float areaJ = (x2 - x1 + 1.f) * (y2 - y1 + 1.f);
        float iw = fminf(bx2, x2) - fmaxf(bx1, x1) + 1.f;
        float ih = fminf(by2, y2) - fmaxf(by1, y1) + 1.f;
        iw = fmaxf(iw, 0.f); ih = fmaxf(ih, 0.f);
        float inter = iw * ih;
        float iou = inter / (areaJ + areaI - inter);
        if (iou > NMS_TH) m |= (1ULL << jj);
    }
    g_iou[(size_t)i * NWORDS + wb] = m;
}

// ---------------- serial greedy NMS over bitmask (one block) ----------------
__global__ void nms_kernel() {
    __shared__ unsigned long long rem[NWORDS];
    __shared__ int s_cur, s_pos, s_nk;
    int tid = threadIdx.x;
    if (tid < NWORDS) rem[tid] = 0ULL;
    if (tid == 0) { s_pos = 0; s_nk = 0; }
    __syncthreads();
    while (true) {
        if (tid == 0) {
            s_cur = -1;
            if (s_nk < POST_NMS) {
                int p = s_pos;
                while (p < PRE_NMS) {
                    int w = p >> 6;
                    unsigned long long avail = ~rem[w];
                    avail &= (~0ULL) << (p & 63);
                    if (w == NWORDS - 1) avail &= ((1ULL << 48) - 1ULL);
                    if (avail) {
                        p = (w << 6) + __ffsll((long long)avail) - 1;
                        s_cur = p;
                        s_pos = p + 1;
                        g_keep[s_nk] = p;
                        s_nk = s_nk + 1;
                        break;
                    }
                    p = (w + 1) << 6;
                }
            }
        }
        __syncthreads();
        int cur = s_cur;
        if (cur < 0) break;
        if (tid < NWORDS) rem[tid] |= g_iou[(size_t)cur * NWORDS + tid];
        __syncthreads();
    }
    if (tid == 0) g_numKeep = s_nk;
}

// ---------------- assemble output (1000 x 6) ----------------
__global__ void output_kernel(float* __restrict__ out) {
    int i = blockIdx.x * blockDim.x + threadIdx.x;
    if (i >= POST_NMS) return;
    float x1 = 0, y1 = 0, x2 = 0, y2 = 0, s = 0;
    int nk = g_numKeep;
    if (i < nk) {
        int k = g_keep[i];
        x1 = g_boxes[k * 4 + 0]; y1 = g_boxes[k * 4 + 1];
        x2 = g_boxes[k * 4 + 2]; y2 = g_boxes[k * 4 + 3];
        s = g_selScore[k];
    }
    out[i * 6 + 0] = 0.f;
    out[i * 6 + 1] = x1;
    out[i * 6 + 2] = y1;
    out[i * 6 + 3] = x2;
    out[i * 6 + 4] = y2;
    out[i * 6 + 5] = s;
}

// ---------------- launch ----------------
extern "C" void kernel_launch(void* const* d_in, const int* in_sizes, int n_in,
                              void* d_out, int out_size) {
    const float* feats[5];
    for (int i = 0; i < 5; i++) feats[i] = (const float*)d_in[i];
    const float* im_info = (const float*)d_in[5];
    const float* convW = (const float*)d_in[6];
    const float* convB = (const float*)d_in[7];
    const float* sw = (const float*)d_in[8];
    const float* sb = (const float*)d_in[9];
    const float* bw = (const float*)d_in[10];
    const float* bb = (const float*)d_in[11];
    float* out = (float*)d_out;

    static const int Hs[5] = {128, 64, 32, 16, 8};
    static const int Ws[5] = {208, 104, 52, 26, 13};
    static const int pixBase[5] = {0, 26624, 33280, 34944, 35360};

    repack_kernel<<<512, 256>>>(convW);
    for (int l = 0; l < 5; l++) {
        int HW = Hs[l] * Ws[l];
        dim3 grid(1, (HW + 127) / 128, 8);
        conv3x3_kernel<<<grid, 256>>>(feats[l], convB, Hs[l], Ws[l], pixBase[l]);
    }
    heads_kernel<<<(NPIX * 32 + 255) / 256, 256>>>(sw, sb, bw, bb);
    reset_kernel<<<1, 256>>>();
    const int shifts[4] = {24, 16, 8, 0};
    for (int s = 0; s < 4; s++) {
        hist_kernel<<<416, 256>>>(shifts[s]);
        select_kernel<<<1, 256>>>(shifts[s]);
    }
    compact_kernel<<<416, 256>>>();
    cudaFuncSetAttribute(sort_kernel, cudaFuncAttributeMaxDynamicSharedMemorySize,
                         CAND_MAX * 8);
    sort_kernel<<<1, 1024, CAND_MAX * 8>>>();
    decode_kernel<<<(PRE_NMS + 255) / 256, 256>>>(im_info);
    iou_kernel<<<(PRE_NMS * NWORDS + 255) / 256, 256>>>();
    nms_kernel<<<1, 128>>>();
    output_kernel<<<(POST_NMS + 255) / 256, 256>>>(out);
}

// round 7
// speedup vs baseline: 1.2695x; 1.2695x over previous
#include <cuda_runtime.h>
#include <cuda_bf16.h>
#include <math.h>
#include <stdint.h>

#define NPIX 35464
#define NANCH 106392
#define PRE_NMS 6000
#define POOL_K 6656
#define POOLMAX 8192
#define POST_NMS 1000
#define NMS_TH 0.7f
#define CAND_MAX 8192
#define NWORDS 94    // ceil(6000/64)
#define KPACK 6912   // 3 segments x 2304
#define KTILES 216   // 6912 / 32

// ---------------- device scratch ----------------
__device__ float g_f[(size_t)NPIX * 512];             // features (approx, then exact rows)
__device__ float g_fp[(size_t)NPIX * 256];            // exact fp32 input, pixel-major
__device__ __nv_bfloat16 g_f0[(size_t)NPIX * 256];    // bf16 hi
__device__ __nv_bfloat16 g_f1[(size_t)NPIX * 256];    // bf16 lo
__device__ __nv_bfloat16 g_wp[(size_t)512 * KPACK];   // packed bf16 weights
__device__ float g_wT[2304 * 512];                    // fp32 weights [k][oc]
__device__ unsigned g_keys[NANCH];
__device__ float g_deltas[(size_t)NANCH * 4];
__device__ unsigned g_hist[256];
__device__ unsigned g_prefix;
__device__ int g_remaining;
__device__ int g_candCount;
__device__ unsigned long long g_cand[CAND_MAX];
__device__ int g_pixFlag[NPIX];
__device__ int g_poolPix[POOLMAX];
__device__ int g_poolCnt;
__device__ int g_selIdx[PRE_NMS];
__device__ float g_selScore[PRE_NMS];
__device__ float g_boxes[PRE_NMS * 4];
__device__ unsigned long long g_iou[(size_t)PRE_NMS * NWORDS];
__device__ int g_keep[POST_NMS];
__device__ int g_numKeep;

// constants
__constant__ int c_aoff[6] = {0, 79872, 99840, 104832, 106080, 106392};
__constant__ int c_W[5] = {208, 104, 52, 26, 13};
__constant__ int c_H[5] = {128, 64, 32, 16, 8};
__constant__ int c_stride[5] = {4, 8, 16, 32, 64};
__constant__ int c_pixBase[5] = {0, 26624, 33280, 34944, 35360};
__constant__ int c_cumTiles[6] = {0, 208, 260, 273, 277, 278};  // 128-pixel tiles
__constant__ int c_ws0[15] = {6,4,3, 11,8,6, 23,16,11, 45,32,23, 91,64,45};
__constant__ int c_hs0[15] = {3,4,6, 6,8,12, 12,16,22, 22,32,46, 46,64,90};

// ---------------- small asm helpers ----------------
__device__ __forceinline__ uint32_t smem_u32(const void* p) {
    uint32_t a;
    asm("{ .reg .u64 t; cvta.to.shared.u64 t, %1; cvt.u32.u64 %0, t; }" : "=r"(a) : "l"(p));
    return a;
}
__device__ __forceinline__ void cp16(uint32_t dst, const void* src, uint32_t bytes) {
    asm volatile("cp.async.cg.shared.global [%0], [%1], 16, %2;"
                 :: "r"(dst), "l"(src), "r"(bytes) : "memory");
}
__device__ __forceinline__ void ldmx4(uint32_t a, uint32_t& r0, uint32_t& r1,
                                      uint32_t& r2, uint32_t& r3) {
    asm volatile("ldmatrix.sync.aligned.m8n8.x4.shared.b16 {%0,%1,%2,%3}, [%4];"
                 : "=r"(r0), "=r"(r1), "=r"(r2), "=r"(r3) : "r"(a));
}
__device__ __forceinline__ void mma16816(float* c, const uint32_t* a,
                                         uint32_t b0, uint32_t b1) {
    asm volatile(
        "mma.sync.aligned.m16n8k16.row.col.f32.bf16.bf16.f32 "
        "{%0,%1,%2,%3}, {%4,%5,%6,%7}, {%8,%9}, {%0,%1,%2,%3};"
        : "+f"(c[0]), "+f"(c[1]), "+f"(c[2]), "+f"(c[3])
        : "r"(a[0]), "r"(a[1]), "r"(a[2]), "r"(a[3]), "r"(b0), "r"(b1));
}

// ---------------- prep: NCHW fp32 -> pixel-major fp32 + bf16 hi/lo ----------------
__global__ void prep_kernel(const float* __restrict__ f, int HW, int base) {
    __shared__ float sh[32][33];
    int pix0 = blockIdx.x * 32, ic0 = blockIdx.y * 32;
    int tx = threadIdx.x, ty = threadIdx.y;
    int p = pix0 + tx;
    sh[ty][tx] = (p < HW) ? f[(size_t)(ic0 + ty) * HW + p] : 0.f;
    __syncthreads();
    int pw = pix0 + ty;
    if (pw < HW) {
        float v = sh[tx][ty];
        __nv_bfloat16 hi = __float2bfloat16_rn(v);
        float lo = v - __bfloat162float(hi);
        size_t o = (size_t)(base + pw) * 256 + ic0 + tx;
        g_fp[o] = v;
        g_f0[o] = hi;
        g_f1[o] = __float2bfloat16_rn(lo);
    }
}

// ---------------- weight pack: bf16 [W0|W1|W0] + fp32 transposed [k][oc] ----------------
__global__ void repackw_kernel(const float* __restrict__ w) {
    int t = blockIdx.x * blockDim.x + threadIdx.x;
    if (t >= 512 * 2304) return;
    int oc = t / 2304, k = t - oc * 2304;
    int tap = k >> 8, ic = k & 255;
    float v = w[oc * 2304 + ic * 9 + tap];
    __nv_bfloat16 w0 = __float2bfloat16_rn(v);
    __nv_bfloat16 w1 = __float2bfloat16_rn(v - __bfloat162float(w0));
    size_t b = (size_t)oc * KPACK;
    g_wp[b + 0 * 2304 + k] = w0;   // A0*W0
    g_wp[b + 1 * 2304 + k] = w1;   // A0*W1
    g_wp[b + 2 * 2304 + k] = w0;   // A1*W0
    g_wT[k * 512 + oc] = v;
}

// ---------------- approx conv via mma.sync bf16 (3-term split) ----------------
#define ASTRIDE 40   // bf16 elems per row (64B data + 16B pad)

__global__ void __launch_bounds__(256, 2) conv_mma_kernel(const float* __restrict__ bias) {
    __shared__ __nv_bfloat16 sA[2][128][ASTRIDE];
    __shared__ __nv_bfloat16 sB[2][128][ASTRIDE];
    __shared__ float s_bias[128];

    const int tid = threadIdx.x;
    const int mt = blockIdx.x >> 2;
    const int oc0 = (blockIdx.x & 3) << 7;

    int l = 0;
    while (l < 4 && mt >= c_cumTiles[l + 1]) l++;
    const int Wl = c_W[l], Hl = c_H[l];
    const int HWl = Wl * Hl;
    const int lvlBase = c_pixBase[l];
    const int pixLocal0 = (mt - c_cumTiles[l]) << 7;

    if (tid < 128) s_bias[tid] = bias[oc0 + tid];

    const int r0 = tid >> 2;
    const int r1 = r0 + 64;
    const int q = tid & 3;
    int pl0 = pixLocal0 + r0, pl1 = pixLocal0 + r1;
    bool pv0 = pl0 < HWl, pv1 = pl1 < HWl;
    int py0 = pv0 ? pl0 / Wl : 0; int px0 = pl0 - py0 * Wl;
    int py1 = pv1 ? pl1 / Wl : 0; int px1 = pl1 - py1 * Wl;

    const uint32_t aBase = smem_u32(&sA[0][0][0]);
    const uint32_t bBase = smem_u32(&sB[0][0][0]);
    const uint32_t stageBytes = 128 * ASTRIDE * 2;

    const int wid = tid >> 5, lane = tid & 31;
    const int warpM = wid >> 1, warpN = wid & 1;
    const int m0 = warpM * 32, n0 = warpN * 64;

    float acc[2][8][4];
#pragma unroll
    for (int mi = 0; mi < 2; mi++)
#pragma unroll
        for (int ni = 0; ni < 8; ni++)
#pragma unroll
            for (int j = 0; j < 4; j++) acc[mi][ni][j] = 0.f;

    const uint32_t aRow = (lane & 15);
    const uint32_t aColB = ((lane & 16) ? 8 : 0) * 2;
    const uint32_t bRow = (lane & 7) + ((lane & 16) ? 8 : 0);
    const uint32_t bColB = ((lane & 8) ? 8 : 0) * 2;

    auto loadTile = [&](int it, int buf) {
        const int k0 = it * 32;
        const int seg = it / 72;
        const int rem = k0 - seg * 2304;
        const int tap = rem >> 8;
        const int icb = (rem & 255) + q * 8;
        const int dy = tap / 3 - 1;
        const int dx = tap - (tap / 3) * 3 - 1;
        const __nv_bfloat16* fsrc = (seg < 2) ? g_f0 : g_f1;
        {
            int iy = py0 + dy, ix = px0 + dx;
            bool v = pv0 && ((unsigned)iy < (unsigned)Hl) && ((unsigned)ix < (unsigned)Wl);
            const __nv_bfloat16* src = fsrc + (((size_t)(lvlBase + iy * Wl + ix)) << 8) + icb;
            cp16(aBase + buf * stageBytes + (r0 * ASTRIDE + q * 8) * 2, src, v ? 16u : 0u);
        }
        {
            int iy = py1 + dy, ix = px1 + dx;
            bool v = pv1 && ((unsigned)iy < (unsigned)Hl) && ((unsigned)ix < (unsigned)Wl);
            const __nv_bfloat16* src = fsrc + (((size_t)(lvlBase + iy * Wl + ix)) << 8) + icb;
            cp16(aBase + buf * stageBytes + (r1 * ASTRIDE + q * 8) * 2, src, v ? 16u : 0u);
        }
        cp16(bBase + buf * stageBytes + (r0 * ASTRIDE + q * 8) * 2,
             g_wp + (size_t)(oc0 + r0) * KPACK + k0 + q * 8, 16u);
        cp16(bBase + buf * stageBytes + (r1 * ASTRIDE + q * 8) * 2,
             g_wp + (size_t)(oc0 + r1) * KPACK + k0 + q * 8, 16u);
        asm volatile("cp.async.commit_group;" ::: "memory");
    };

    loadTile(0, 0);

    for (int it = 0; it < KTILES; ++it) {
        const int buf = it & 1;
        if (it + 1 < KTILES) {
            loadTile(it + 1, buf ^ 1);
            asm volatile("cp.async.wait_group 1;" ::: "memory");
        } else {
            asm volatile("cp.async.wait_group 0;" ::: "memory");
        }
        __syncthreads();

        const uint32_t aS = aBase + buf * stageBytes;
        const uint32_t bS = bBase + buf * stageBytes;
#pragma unroll
        for (int kq = 0; kq < 2; kq++) {
            uint32_t afr[2][4];
#pragma unroll
            for (int mi = 0; mi < 2; mi++) {
                uint32_t addr = aS + (uint32_t)(m0 + mi * 16 + aRow) * (ASTRIDE * 2)
                              + (uint32_t)kq * 32 + aColB;
                ldmx4(addr, afr[mi][0], afr[mi][1], afr[mi][2], afr[mi][3]);
            }
            uint32_t bfr[4][4];
#pragma unroll
            for (int g = 0; g < 4; g++) {
                uint32_t addr = bS + (uint32_t)(n0 + g * 16 + bRow) * (ASTRIDE * 2)
                              + (uint32_t)kq * 32 + bColB;
                ldmx4(addr, bfr[g][0], bfr[g][1], bfr[g][2], bfr[g][3]);
            }
#pragma unroll
            for (int mi = 0; mi < 2; mi++)
#pragma unroll
                for (int ni = 0; ni < 8; ni++)
                    mma16816(acc[mi][ni], afr[mi],
                             bfr[ni >> 1][(ni & 1) * 2], bfr[ni >> 1][(ni & 1) * 2 + 1]);
        }
        __syncthreads();
    }

#pragma unroll
    for (int mi = 0; mi < 2; mi++) {
        int rowA = pixLocal0 + m0 + mi * 16 + (lane >> 2);
        int rowB = rowA + 8;
        int colL = n0 + (lane & 3) * 2;
#pragma unroll
        for (int ni = 0; ni < 8; ni++) {
            int col = colL + ni * 8;
            float b0 = s_bias[col], b1 = s_bias[col + 1];
            if (rowA < HWl) {
                float2 o = make_float2(acc[mi][ni][0] + b0, acc[mi][ni][1] + b1);
                *(float2*)(g_f + (size_t)(lvlBase + rowA) * 512 + oc0 + col) = o;
            }
            if (rowB < HWl) {
                float2 o = make_float2(acc[mi][ni][2] + b0, acc[mi][ni][3] + b1);
                *(float2*)(g_f + (size_t)(lvlBase + rowB) * 512 + oc0 + col) = o;
            }
        }
    }
}

// ---------------- heads core (shared by approx and exact passes) ----------------
__device__ __forceinline__ void heads_pixel(int gw, int lane,
        const float* __restrict__ sw, const float* __restrict__ sb,
        const float* __restrict__ bw, const float* __restrict__ bb)
{
    const float* f = g_f + (size_t)gw * 512;
    float4 v[4];
#pragma unroll
    for (int j = 0; j < 4; j++)
        v[j] = *(const float4*)(f + j * 128 + lane * 4);

    float c[6];
#pragma unroll
    for (int ch = 0; ch < 6; ch++) {
        const float* w = sw + ch * 512;
        float s = 0.f;
#pragma unroll
        for (int j = 0; j < 4; j++) {
            float4 ww = *(const float4*)(w + j * 128 + lane * 4);
            s += v[j].x * ww.x + v[j].y * ww.y + v[j].z * ww.z + v[j].w * ww.w;
        }
#pragma unroll
        for (int off = 16; off; off >>= 1) s += __shfl_xor_sync(0xffffffffu, s, off);
        c[ch] = s + sb[ch];
    }
    float d[12];
#pragma unroll
    for (int ch = 0; ch < 12; ch++) {
        const float* w = bw + ch * 512;
        float s = 0.f;
#pragma unroll
        for (int j = 0; j < 4; j++) {
            float4 ww = *(const float4*)(w + j * 128 + lane * 4);
            s += v[j].x * ww.x + v[j].y * ww.y + v[j].z * ww.z + v[j].w * ww.w;
        }
#pragma unroll
        for (int off = 16; off; off >>= 1) s += __shfl_xor_sync(0xffffffffu, s, off);
        d[ch] = s + bb[ch];
    }
    int base = gw * 3;
    if (lane < 3) {
        float s = 1.f / (1.f + expf(c[lane] - c[3 + lane]));
        unsigned bits = __float_as_uint(s);
        unsigned key = bits ^ ((unsigned)((int)bits >> 31) | 0x80000000u);
        g_keys[base + lane] = key;
    }
    if (lane < 12) {
        g_deltas[(size_t)base * 4 + lane] = d[lane];
    }
}

__global__ void heads_kernel(const float* __restrict__ sw, const float* __restrict__ sb,
                             const float* __restrict__ bw, const float* __restrict__ bb)
{
    int gw = (blockIdx.x * blockDim.x + threadIdx.x) >> 5;
    int lane = threadIdx.x & 31;
    if (gw >= NPIX) return;
    heads_pixel(gw, lane, sw, sb, bw, bb);
}

__global__ void heads_pool_kernel(const float* __restrict__ sw, const float* __restrict__ sb,
                                  const float* __restrict__ bw, const float* __restrict__ bb)
{
    int i = (blockIdx.x * blockDim.x + threadIdx.x) >> 5;
    int lane = threadIdx.x & 31;
    if (i >= g_poolCnt) return;
    heads_pixel(g_poolPix[i], lane, sw, sb, bw, bb);
}

// ---------------- pool marking / compaction ----------------
__global__ void zero_flags_kernel() {
    int i = blockIdx.x * blockDim.x + threadIdx.x;
    if (i < NPIX) g_pixFlag[i] = 0;
    if (i == 0) g_poolCnt = 0;
}

__global__ void mark_pool_kernel() {
    unsigned T = g_prefix;
    for (int i = blockIdx.x * blockDim.x + threadIdx.x; i < NANCH;
         i += gridDim.x * blockDim.x) {
        if (g_keys[i] >= T) g_pixFlag[i / 3] = 1;
    }
}

__global__ void compact_pix_kernel() {
    for (int i = blockIdx.x * blockDim.x + threadIdx.x; i < NPIX;
         i += gridDim.x * blockDim.x) {
        if (g_pixFlag[i]) {
            int p = atomicAdd(&g_poolCnt, 1);
            if (p < POOLMAX) g_poolPix[p] = i;
        }
    }
}

// ---------------- exact fp32 recompute of pool pixels (R1-identical chain) ----------------
// grid (256, 8), 256 threads. Tile: 32 pixels x 64 oc. lane = pixel, warp = 8-oc group.
__global__ void __launch_bounds__(256) exact_conv_kernel(const float* __restrict__ bias) {
    __shared__ float sA[32][33];
    __shared__ float sW[32][68];
    __shared__ int s_pix[32], s_base[32], s_W[32], s_H[32], s_py[32], s_px[32];

    const int tid = threadIdx.x;
    const int cnt = g_poolCnt < POOLMAX ? g_poolCnt : POOLMAX;
    const int ptile = blockIdx.x;
    if (ptile * 32 >= cnt) return;
    const int oc0 = blockIdx.y * 64;

    if (tid < 32) {
        int idx = ptile * 32 + tid;
        int pix = (idx < cnt) ? g_poolPix[idx] : -1;
        s_pix[tid] = pix;
        if (pix >= 0) {
            int l = 0;
            while (l < 4 && pix >= c_pixBase[l + 1]) l++;
            int local = pix - c_pixBase[l];
            int Wl = c_W[l];
            s_base[tid] = c_pixBase[l];
            s_W[tid] = Wl;
            s_H[tid] = c_H[l];
            s_py[tid] = local / Wl;
            s_px[tid] = local - (local / Wl) * Wl;
        }
    }
    __syncthreads();

    const int lane = tid & 31, w8 = (tid >> 5) * 8;
    const int p8 = tid >> 3;            // pixel slot for loads
    const int kq = (tid & 7) * 4;       // ic sub-offset for A loads
    const int wkk = tid >> 3;           // k row for W loads
    const int wog = (tid & 7) * 8;      // oc group for W loads

    float acc[8];
#pragma unroll
    for (int j = 0; j < 8; j++) acc[j] = 0.f;

    for (int chunk = 0; chunk < 72; chunk++) {
        const int tap = chunk >> 3;
        const int ic0 = (chunk & 7) * 32;
        const int dy = tap / 3 - 1;
        const int dx = tap - (tap / 3) * 3 - 1;
        const int k0 = chunk * 32;
        // A: 32 pixels x 32 ic
        {
            float4 val = make_float4(0.f, 0.f, 0.f, 0.f);
            int pix = s_pix[p8];
            if (pix >= 0) {
                int iy = s_py[p8] + dy, ix = s_px[p8] + dx;
                if ((unsigned)iy < (unsigned)s_H[p8] && (unsigned)ix < (unsigned)s_W[p8]) {
                    int np = s_base[p8] + iy * s_W[p8] + ix;
                    val = *(const float4*)(g_fp + (size_t)np * 256 + ic0 + kq);
                }
            }
            sA[p8][kq + 0] = val.x;
            sA[p8][kq + 1] = val.y;
            sA[p8][kq + 2] = val.z;
            sA[p8][kq + 3] = val.w;
        }
        // W: 32 k x 64 oc from g_wT [k][oc]
        {
            const float* src = g_wT + (size_t)(k0 + wkk) * 512 + oc0 + wog;
            float4 v0 = *(const float4*)(src);
            float4 v1 = *(const float4*)(src + 4);
            *(float4*)(&sW[wkk][wog]) = v0;
            *(float4*)(&sW[wkk][wog + 4]) = v1;
        }
        __syncthreads();
#pragma unroll 8
        for (int kk = 0; kk < 32; kk++) {
            float a = sA[lane][kk];
#pragma unroll
            for (int j = 0; j < 8; j++)
                acc[j] = fmaf(a, sW[kk][w8 + j], acc[j]);
        }
        __syncthreads();
    }

    int pix = s_pix[lane];
    if (pix >= 0) {
        float* o = g_f + (size_t)pix * 512 + oc0 + w8;
#pragma unroll
        for (int j = 0; j < 8; j++) o[j] = acc[j] + bias[oc0 + w8 + j];
    }
}

// ---------------- radix top-k threshold selection ----------------
__global__ void reset_kernel(int k) {
    int t = threadIdx.x;
    if (t < 256) g_hist[t] = 0;
    if (t == 0) { g_prefix = 0; g_remaining = k; g_candCount = 0; g_numKeep = 0; }
}

__global__ void hist_kernel(int shift) {
    __shared__ unsigned sh[256];
    if (threadIdx.x < 256) sh[threadIdx.x] = 0;
    __syncthreads();
    unsigned pfx = g_prefix;
    for (int i = blockIdx.x * blockDim.x + threadIdx.x; i < NANCH;
         i += gridDim.x * blockDim.x) {
        unsigned k = g_keys[i];
        bool ok = (shift == 24) || ((k >> (shift + 8)) == (pfx >> (shift + 8)));
        if (ok) atomicAdd(&sh[(k >> shift) & 255u], 1u);
    }
    __syncthreads();
    if (threadIdx.x < 256 && sh[threadIdx.x])
        atomicAdd(&g_hist[threadIdx.x], sh[threadIdx.x]);
}

__global__ void select_kernel(int shift) {
    if (threadIdx.x == 0) {
        int rem = g_remaining;
        unsigned cum = 0;
        for (int b = 255; b >= 0; b--) {
            unsigned h = g_hist[b];
            if (cum + h >= (unsigned)rem) {
                g_prefix |= ((unsigned)b) << shift;
                g_remaining = rem - (int)cum;
                break;
            }
            cum += h;
        }
    }
    __syncthreads();
    if (threadIdx.x < 256) g_hist[threadIdx.x] = 0;
}

__global__ void compact_kernel() {
    unsigned T = g_prefix;
    for (int i = blockIdx.x * blockDim.x + threadIdx.x; i < NANCH;
         i += gridDim.x * blockDim.x) {
        unsigned k = g_keys[i];
        if (k >= T) {
            int p = atomicAdd(&g_candCount, 1);
            if (p < CAND_MAX)
                g_cand[p] = ((unsigned long long)k << 32) | (unsigned)(~i);
        }
    }
}

// ---------------- bitonic sort of candidates (key desc, idx asc) ----------------
__global__ void sort_kernel() {
    extern __shared__ unsigned long long s[];
    int tid = threadIdx.x;
    int cnt = g_candCount;
    if (cnt > CAND_MAX) cnt = CAND_MAX;
    for (int i = tid; i < CAND_MAX; i += blockDim.x)
        s[i] = (i < cnt) ? g_cand[i] : 0ULL;
    __syncthreads();
    for (int k = 2; k <= CAND_MAX; k <<= 1) {
        for (int j = k >> 1; j > 0; j >>= 1) {
            for (int i = tid; i < CAND_MAX; i += blockDim.x) {
                int ixj = i ^ j;
                if (ixj > i) {
                    unsigned long long a = s[i], b = s[ixj];
                    bool desc = ((i & k) == 0);
                    if (desc ? (a < b) : (a > b)) { s[i] = b; s[ixj] = a; }
                }
            }
            __syncthreads();
        }
    }
    for (int i = tid; i < PRE_NMS; i += blockDim.x) {
        unsigned long long e = s[i];
        unsigned idx = ~(unsigned)(e & 0xffffffffu);
        unsigned key = (unsigned)(e >> 32);
        unsigned bits = (key & 0x80000000u) ? (key ^ 0x80000000u) : ~key;
        g_selIdx[i] = (int)idx;
        g_selScore[i] = __uint_as_float(bits);
    }
}

// ---------------- decode + clip only selected 6000 ----------------
__global__ void decode_kernel(const float* __restrict__ im_info) {
    int i = blockIdx.x * blockDim.x + threadIdx.x;
    if (i >= PRE_NMS) return;
    int idx = g_selIdx[i];
    int l = 0;
    while (l < 4 && idx >= c_aoff[l + 1]) l++;
    int local = idx - c_aoff[l];
    int p = local / 3, a = local - p * 3;
    int W = c_W[l];
    int y = p / W, x = p - y * W;
    float stride = (float)c_stride[l];
    float cb = (stride - 1.f) * 0.5f;
    float ws = c_ws0[l * 3 + a] * 8.f, hs = c_hs0[l * 3 + a] * 8.f;
    float sx = x * stride, sy = y * stride;
    float ax1 = sx + cb - 0.5f * (ws - 1.f);
    float ay1 = sy + cb - 0.5f * (hs - 1.f);
    float ax2 = sx + cb + 0.5f * (ws - 1.f);
    float ay2 = sy + cb + 0.5f * (hs - 1.f);
    float w = ax2 - ax1 + 1.f, h = ay2 - ay1 + 1.f;
    float cx = ax1 + 0.5f * w, cy = ay1 + 0.5f * h;
    const float* dd = g_deltas + (size_t)idx * 4;
    float pcx = dd[0] * w + cx;
    float pcy = dd[1] * h + cy;
    float pw = expf(dd[2]) * w;
    float ph = expf(dd[3]) * h;
    float imW = im_info[1] - 1.f, imH = im_info[0] - 1.f;
    g_boxes[i * 4 + 0] = fminf(fmaxf(pcx - 0.5f * pw, 0.f), imW);
    g_boxes[i * 4 + 1] = fminf(fmaxf(pcy - 0.5f * ph, 0.f), imH);
    g_boxes[i * 4 + 2] = fminf(fmaxf(pcx + 0.5f * pw, 0.f), imW);
    g_boxes[i * 4 + 3] = fminf(fmaxf(pcy + 0.5f * ph, 0.f), imH);
}

// ---------------- IoU suppression bitmask ----------------
__global__ void iou_kernel() {
    int t = blockIdx.x * blockDim.x + threadIdx.x;
    if (t >= PRE_NMS * NWORDS) return;
    int i = t / NWORDS, wb = t - i * NWORDS;
    float bx1 = g_boxes[i * 4], by1 = g_boxes[i * 4 + 1];
    float bx2 = g_boxes[i * 4 + 2], by2 = g_boxes[i * 4 + 3];
    float areaI = (bx2 - bx1 + 1.f) * (by2 - by1 + 1.f);
    unsigned long long m = 0;
    int j0 = wb * 64;
    int jend = PRE_NMS - j0; if (jend > 64) jend = 64;
    for (int jj = 0; jj < jend; jj++) {
        int j = j0 + jj;
        float x1 = g_boxes[j * 4], y1 = g_boxes[j * 4 + 1];
        float x2 = g_boxes[j * 4 + 2], y2 = g_boxes[j * 4 + 3];
        float areaJ = (x2 - x1 + 1.f) * (y2 - y1 + 1.f);
        float iw = fminf(bx2, x2) - fmaxf(bx1, x1) + 1.f;
        float ih = fminf(by2, y2) - fmaxf(by1, y1) + 1.f;
        iw = fmaxf(iw, 0.f); ih = fmaxf(ih, 0.f);
        float inter = iw * ih;
        float iou = inter / (areaJ + areaI - inter);
        if (iou > NMS_TH) m |= (1ULL << jj);
    }
    g_iou[(size_t)i * NWORDS + wb] = m;
}

// ---------------- serial greedy NMS over bitmask (one block) ----------------
__global__ void nms_kernel() {
    __shared__ unsigned long long rem[NWORDS];
    __shared__ int s_cur, s_pos, s_nk;
    int tid = threadIdx.x;
    if (tid < NWORDS) rem[tid] = 0ULL;
    if (tid == 0) { s_pos = 0; s_nk = 0; }
    __syncthreads();
    while (true) {
        if (tid == 0) {
            s_cur = -1;
            if (s_nk < POST_NMS) {
                int p = s_pos;
                while (p < PRE_NMS) {
                    int w = p >> 6;
                    unsigned long long avail = ~rem[w];
                    avail &= (~0ULL) << (p & 63);
                    if (w == NWORDS - 1) avail &= ((1ULL << 48) - 1ULL);
                    if (avail) {
                        p = (w << 6) + __ffsll((long long)avail) - 1;
                        s_cur = p;
                        s_pos = p + 1;
                        g_keep[s_nk] = p;
                        s_nk = s_nk + 1;
                        break;
                    }
                    p = (w + 1) << 6;
                }
            }
        }
        __syncthreads();
        int cur = s_cur;
        if (cur < 0) break;
        if (tid < NWORDS) rem[tid] |= g_iou[(size_t)cur * NWORDS + tid];
        __syncthreads();
    }
    if (tid == 0) g_numKeep = s_nk;
}

// ---------------- assemble output (1000 x 6) ----------------
__global__ void output_kernel(float* __restrict__ out) {
    int i = blockIdx.x * blockDim.x + threadIdx.x;
    if (i >= POST_NMS) return;
    float x1 = 0, y1 = 0, x2 = 0, y2 = 0, s = 0;
    int nk = g_numKeep;
    if (i < nk) {
        int k = g_keep[i];
        x1 = g_boxes[k * 4 + 0]; y1 = g_boxes[k * 4 + 1];
        x2 = g_boxes[k * 4 + 2]; y2 = g_boxes[k * 4 + 3];
        s = g_selScore[k];
    }
    out[i * 6 + 0] = 0.f;
    out[i * 6 + 1] = x1;
    out[i * 6 + 2] = y1;
    out[i * 6 + 3] = x2;
    out[i * 6 + 4] = y2;
    out[i * 6 + 5] = s;
}

// ---------------- launch ----------------
extern "C" void kernel_launch(void* const* d_in, const int* in_sizes, int n_in,
                              void* d_out, int out_size) {
    const float* feats[5];
    for (int i = 0; i < 5; i++) feats[i] = (const float*)d_in[i];
    const float* im_info = (const float*)d_in[5];
    const float* convW = (const float*)d_in[6];
    const float* convB = (const float*)d_in[7];
    const float* sw = (const float*)d_in[8];
    const float* sb = (const float*)d_in[9];
    const float* bw = (const float*)d_in[10];
    const float* bb = (const float*)d_in[11];
    float* out = (float*)d_out;

    static const int Hs[5] = {128, 64, 32, 16, 8};
    static const int Ws[5] = {208, 104, 52, 26, 13};
    static const int pixBase[5] = {0, 26624, 33280, 34944, 35360};

    static bool attrDone = false;
    if (!attrDone) {
        cudaFuncSetAttribute(sort_kernel,
                             cudaFuncAttributeMaxDynamicSharedMemorySize, CAND_MAX * 8);
        attrDone = true;
    }

    for (int l = 0; l < 5; l++) {
        int HW = Hs[l] * Ws[l];
        dim3 grid((HW + 31) / 32, 8);
        prep_kernel<<<grid, dim3(32, 32)>>>(feats[l], HW, pixBase[l]);
    }
    repackw_kernel<<<(512 * 2304 + 255) / 256, 256>>>(convW);
    conv_mma_kernel<<<278 * 4, 256>>>(convB);
    heads_kernel<<<(NPIX * 32 + 255) / 256, 256>>>(sw, sb, bw, bb);

    const int shifts[4] = {24, 16, 8, 0};
    // pass 1: approx top-POOL_K threshold -> pool pixels
    reset_kernel<<<1, 256>>>(POOL_K);
    for (int s = 0; s < 4; s++) {
        hist_kernel<<<416, 256>>>(shifts[s]);
        select_kernel<<<1, 256>>>(shifts[s]);
    }
    zero_flags_kernel<<<(NPIX + 255) / 256, 256>>>();
    mark_pool_kernel<<<416, 256>>>();
    compact_pix_kernel<<<139, 256>>>();
    // exact recompute of pool pixels (R1-identical numerics)
    exact_conv_kernel<<<dim3(256, 8), 256>>>(convB);
    heads_pool_kernel<<<POOLMAX * 32 / 256, 256>>>(sw, sb, bw, bb);
    // pass 2: exact top-PRE_NMS
    reset_kernel<<<1, 256>>>(PRE_NMS);
    for (int s = 0; s < 4; s++) {
        hist_kernel<<<416, 256>>>(shifts[s]);
        select_kernel<<<1, 256>>>(shifts[s]);
    }
    compact_kernel<<<416, 256>>>();
    sort_kernel<<<1, 1024, CAND_MAX * 8>>>();
    decode_kernel<<<(PRE_NMS + 255) / 256, 256>>>(im_info);
    iou_kernel<<<(PRE_NMS * NWORDS + 255) / 256, 256>>>();
    nms_kernel<<<1, 128>>>();
    output_kernel<<<(POST_NMS + 255) / 256, 256>>>(out);
}

// round 8
// speedup vs baseline: 1.5218x; 1.1988x over previous
#include <cuda_runtime.h>
#include <math.h>
#include <stdint.h>

#define NPIX 35464
#define NANCH 106392
#define PRE_NMS 6000
#define POOL_K 6656
#define POOLMAX 8192
#define POST_NMS 1000
#define NMS_TH 0.7f
#define CAND_MAX 8192
#define NWORDS 94    // ceil(6000/64)

// ---------------- device scratch ----------------
__device__ float g_f[(size_t)NPIX * 512];     // exact features (pool pixels only)
__device__ float g_fp[(size_t)NPIX * 256];    // fp32 input, pixel-major
__device__ float g_wT[2304 * 512];            // fp32 conv weights [k][oc]
__device__ float g_weff[2304 * 6];            // folded conv+score weights [k][ch]
__device__ float g_weffB[6];                  // folded bias
__device__ unsigned g_keys[NANCH];
__device__ float g_deltas[(size_t)NANCH * 4];
__device__ unsigned g_hist[256];
__device__ unsigned g_prefix;
__device__ int g_remaining;
__device__ int g_candCount;
__device__ unsigned long long g_cand[CAND_MAX];
__device__ int g_pixFlag[NPIX];
__device__ int g_poolPix[POOLMAX];
__device__ int g_poolCnt;
__device__ int g_selIdx[PRE_NMS];
__device__ float g_selScore[PRE_NMS];
__device__ float g_boxes[PRE_NMS * 4];
__device__ unsigned long long g_iou[(size_t)PRE_NMS * NWORDS];
__device__ int g_keep[POST_NMS];
__device__ int g_numKeep;

// constants
__constant__ int c_aoff[6] = {0, 79872, 99840, 104832, 106080, 106392};
__constant__ int c_W[5] = {208, 104, 52, 26, 13};
__constant__ int c_H[5] = {128, 64, 32, 16, 8};
__constant__ int c_stride[5] = {4, 8, 16, 32, 64};
__constant__ int c_pixBase[5] = {0, 26624, 33280, 34944, 35360};
__constant__ int c_ws0[15] = {6,4,3, 11,8,6, 23,16,11, 45,32,23, 91,64,45};
__constant__ int c_hs0[15] = {3,4,6, 6,8,12, 12,16,22, 22,32,46, 46,64,90};

// ---------------- prep: NCHW fp32 -> pixel-major fp32 ----------------
__global__ void prep_kernel(const float* __restrict__ f, int HW, int base) {
    __shared__ float sh[32][33];
    int pix0 = blockIdx.x * 32, ic0 = blockIdx.y * 32;
    int tx = threadIdx.x, ty = threadIdx.y;
    int p = pix0 + tx;
    sh[ty][tx] = (p < HW) ? f[(size_t)(ic0 + ty) * HW + p] : 0.f;
    __syncthreads();
    int pw = pix0 + ty;
    if (pw < HW)
        g_fp[(size_t)(base + pw) * 256 + ic0 + tx] = sh[tx][ty];
}

// ---------------- weight transpose: [oc][ic][3][3] -> [k][oc], k=tap*256+ic ----------------
__global__ void repackw_kernel(const float* __restrict__ w) {
    int t = blockIdx.x * blockDim.x + threadIdx.x;
    if (t >= 512 * 2304) return;
    int oc = t / 2304, k = t - oc * 2304;
    int tap = k >> 8, ic = k & 255;
    g_wT[k * 512 + oc] = w[oc * 2304 + ic * 9 + tap];
}

// ---------------- fold score head into conv: W_eff[k][ch], bias ----------------
__global__ void fold_kernel(const float* __restrict__ sw, const float* __restrict__ sb,
                            const float* __restrict__ convB) {
    int t = blockIdx.x * blockDim.x + threadIdx.x;
    if (t < 6) {
        float acc = sb[t];
        for (int oc = 0; oc < 512; oc++) acc += sw[t * 512 + oc] * convB[oc];
        g_weffB[t] = acc;
    }
    if (t >= 2304 * 6) return;
    int k = t / 6, ch = t - k * 6;
    const float* wr = g_wT + (size_t)k * 512;
    const float* sr = sw + ch * 512;
    float acc = 0.f;
    for (int oc = 0; oc < 512; oc += 4)
        acc += wr[oc] * sr[oc] + wr[oc + 1] * sr[oc + 1]
             + wr[oc + 2] * sr[oc + 2] + wr[oc + 3] * sr[oc + 3];
    g_weff[t] = acc;
}

// ---------------- approx scores: folded 3x3x256 -> 6 logits, warp per pixel ----------------
__global__ void __launch_bounds__(256) approx_score_kernel() {
    extern __shared__ float s_w[];   // [2304][8] padded
    __shared__ float s_wb[6];
    int tid = threadIdx.x;
    for (int i = tid; i < 2304 * 6; i += 256) {
        int k = i / 6, ch = i - k * 6;
        s_w[k * 8 + ch] = g_weff[i];
    }
    if (tid < 6) s_wb[tid] = g_weffB[tid];
    __syncthreads();
    int gw = blockIdx.x * 8 + (tid >> 5);
    int lane = tid & 31;
    if (gw >= NPIX) return;
    int l = 0;
    while (l < 4 && gw >= c_pixBase[l + 1]) l++;
    const int Wl = c_W[l], Hl = c_H[l];
    int local = gw - c_pixBase[l];
    int py = local / Wl, px = local - py * Wl;
    float acc[6] = {0.f, 0.f, 0.f, 0.f, 0.f, 0.f};
    const int ic0 = lane * 8;
#pragma unroll
    for (int tap = 0; tap < 9; tap++) {
        int dy = tap / 3 - 1, dx = tap % 3 - 1;
        int iy = py + dy, ix = px + dx;
        if ((unsigned)iy >= (unsigned)Hl || (unsigned)ix >= (unsigned)Wl) continue;
        const float* src = g_fp + ((size_t)(c_pixBase[l] + iy * Wl + ix)) * 256 + ic0;
        float4 v0 = *(const float4*)src;
        float4 v1 = *(const float4*)(src + 4);
        float a[8] = {v0.x, v0.y, v0.z, v0.w, v1.x, v1.y, v1.z, v1.w};
        const float* wp = s_w + (size_t)(tap * 256 + ic0) * 8;
#pragma unroll
        for (int j = 0; j < 8; j++) {
            float4 w0 = *(const float4*)(wp + j * 8);
            float2 w1 = *(const float2*)(wp + j * 8 + 4);
            acc[0] += a[j] * w0.x; acc[1] += a[j] * w0.y; acc[2] += a[j] * w0.z;
            acc[3] += a[j] * w0.w; acc[4] += a[j] * w1.x; acc[5] += a[j] * w1.y;
        }
    }
#pragma unroll
    for (int ch = 0; ch < 6; ch++)
#pragma unroll
        for (int off = 16; off; off >>= 1)
            acc[ch] += __shfl_xor_sync(0xffffffffu, acc[ch], off);
    if (lane < 3) {
        float cb = acc[lane] + s_wb[lane];
        float cf = acc[3 + lane] + s_wb[3 + lane];
        float s = 1.f / (1.f + expf(cb - cf));
        unsigned bits = __float_as_uint(s);
        unsigned key = bits ^ ((unsigned)((int)bits >> 31) | 0x80000000u);
        g_keys[gw * 3 + lane] = key;
    }
}

// ---------------- pool marking ----------------
__global__ void zero_flags_kernel() {
    int i = blockIdx.x * blockDim.x + threadIdx.x;
    if (i < NPIX) g_pixFlag[i] = 0;
    if (i == 0) g_poolCnt = 0;
}

__global__ void mark_compact_kernel() {
    unsigned T = g_prefix;
    for (int i = blockIdx.x * blockDim.x + threadIdx.x; i < NANCH;
         i += gridDim.x * blockDim.x) {
        if (g_keys[i] >= T) {
            int pix = i / 3;
            if (atomicExch(&g_pixFlag[pix], 1) == 0) {
                int p = atomicAdd(&g_poolCnt, 1);
                if (p < POOLMAX) g_poolPix[p] = pix;
            }
        }
    }
}

// ---------------- exact fp32 recompute of pool pixels (R1-identical chain) ----------------
__global__ void __launch_bounds__(256) exact_conv_kernel(const float* __restrict__ bias) {
    __shared__ float sA[32][33];
    __shared__ float sW[32][68];
    __shared__ int s_pix[32], s_base[32], s_W[32], s_H[32], s_py[32], s_px[32];

    const int tid = threadIdx.x;
    const int cnt = g_poolCnt < POOLMAX ? g_poolCnt : POOLMAX;
    const int ptile = blockIdx.x;
    if (ptile * 32 >= cnt) return;
    const int oc0 = blockIdx.y * 64;

    if (tid < 32) {
        int idx = ptile * 32 + tid;
        int pix = (idx < cnt) ? g_poolPix[idx] : -1;
        s_pix[tid] = pix;
        if (pix >= 0) {
            int l = 0;
            while (l < 4 && pix >= c_pixBase[l + 1]) l++;
            int local = pix - c_pixBase[l];
            int Wl = c_W[l];
            s_base[tid] = c_pixBase[l];
            s_W[tid] = Wl;
            s_H[tid] = c_H[l];
            s_py[tid] = local / Wl;
            s_px[tid] = local - (local / Wl) * Wl;
        }
    }
    __syncthreads();

    const int lane = tid & 31, w8 = (tid >> 5) * 8;
    const int p8 = tid >> 3;
    const int kq = (tid & 7) * 4;
    const int wkk = tid >> 3;
    const int wog = (tid & 7) * 8;

    float acc[8];
#pragma unroll
    for (int j = 0; j < 8; j++) acc[j] = 0.f;

    for (int chunk = 0; chunk < 72; chunk++) {
        const int tap = chunk >> 3;
        const int ic0 = (chunk & 7) * 32;
        const int dy = tap / 3 - 1;
        const int dx = tap - (tap / 3) * 3 - 1;
        const int k0 = chunk * 32;
        {
            float4 val = make_float4(0.f, 0.f, 0.f, 0.f);
            int pix = s_pix[p8];
            if (pix >= 0) {
                int iy = s_py[p8] + dy, ix = s_px[p8] + dx;
                if ((unsigned)iy < (unsigned)s_H[p8] && (unsigned)ix < (unsigned)s_W[p8]) {
                    int np = s_base[p8] + iy * s_W[p8] + ix;
                    val = *(const float4*)(g_fp + (size_t)np * 256 + ic0 + kq);
                }
            }
            sA[p8][kq + 0] = val.x;
            sA[p8][kq + 1] = val.y;
            sA[p8][kq + 2] = val.z;
            sA[p8][kq + 3] = val.w;
        }
        {
            const float* src = g_wT + (size_t)(k0 + wkk) * 512 + oc0 + wog;
            float4 v0 = *(const float4*)(src);
            float4 v1 = *(const float4*)(src + 4);
            *(float4*)(&sW[wkk][wog]) = v0;
            *(float4*)(&sW[wkk][wog + 4]) = v1;
        }
        __syncthreads();
#pragma unroll 8
        for (int kk = 0; kk < 32; kk++) {
            float a = sA[lane][kk];
#pragma unroll
            for (int j = 0; j < 8; j++)
                acc[j] = fmaf(a, sW[kk][w8 + j], acc[j]);
        }
        __syncthreads();
    }

    int pix = s_pix[lane];
    if (pix >= 0) {
        float* o = g_f + (size_t)pix * 512 + oc0 + w8;
#pragma unroll
        for (int j = 0; j < 8; j++) o[j] = acc[j] + bias[oc0 + w8 + j];
    }
}

// ---------------- exact heads on pool pixels (R1-identical) ----------------
__device__ __forceinline__ void heads_pixel(int gw, int lane,
        const float* __restrict__ sw, const float* __restrict__ sb,
        const float* __restrict__ bw, const float* __restrict__ bb)
{
    const float* f = g_f + (size_t)gw * 512;
    float4 v[4];
#pragma unroll
    for (int j = 0; j < 4; j++)
        v[j] = *(const float4*)(f + j * 128 + lane * 4);

    float c[6];
#pragma unroll
    for (int ch = 0; ch < 6; ch++) {
        const float* w = sw + ch * 512;
        float s = 0.f;
#pragma unroll
        for (int j = 0; j < 4; j++) {
            float4 ww = *(const float4*)(w + j * 128 + lane * 4);
            s += v[j].x * ww.x + v[j].y * ww.y + v[j].z * ww.z + v[j].w * ww.w;
        }
#pragma unroll
        for (int off = 16; off; off >>= 1) s += __shfl_xor_sync(0xffffffffu, s, off);
        c[ch] = s + sb[ch];
    }
    float d[12];
#pragma unroll
    for (int ch = 0; ch < 12; ch++) {
        const float* w = bw + ch * 512;
        float s = 0.f;
#pragma unroll
        for (int j = 0; j < 4; j++) {
            float4 ww = *(const float4*)(w + j * 128 + lane * 4);
            s += v[j].x * ww.x + v[j].y * ww.y + v[j].z * ww.z + v[j].w * ww.w;
        }
#pragma unroll
        for (int off = 16; off; off >>= 1) s += __shfl_xor_sync(0xffffffffu, s, off);
        d[ch] = s + bb[ch];
    }
    int base = gw * 3;
    if (lane < 3) {
        float s = 1.f / (1.f + expf(c[lane] - c[3 + lane]));
        unsigned bits = __float_as_uint(s);
        unsigned key = bits ^ ((unsigned)((int)bits >> 31) | 0x80000000u);
        g_keys[base + lane] = key;
    }
    if (lane < 12) {
        g_deltas[(size_t)base * 4 + lane] = d[lane];
    }
}

__global__ void heads_pool_kernel(const float* __restrict__ sw, const float* __restrict__ sb,
                                  const float* __restrict__ bw, const float* __restrict__ bb)
{
    int i = (blockIdx.x * blockDim.x + threadIdx.x) >> 5;
    int lane = threadIdx.x & 31;
    if (i >= g_poolCnt) return;
    heads_pixel(g_poolPix[i], lane, sw, sb, bw, bb);
}

// ---------------- radix top-k threshold selection ----------------
__global__ void reset_kernel(int k) {
    int t = threadIdx.x;
    if (t < 256) g_hist[t] = 0;
    if (t == 0) { g_prefix = 0; g_remaining = k; g_candCount = 0; g_numKeep = 0; }
}

__global__ void hist_kernel(int shift) {
    __shared__ unsigned sh[256];
    if (threadIdx.x < 256) sh[threadIdx.x] = 0;
    __syncthreads();
    unsigned pfx = g_prefix;
    for (int i = blockIdx.x * blockDim.x + threadIdx.x; i < NANCH;
         i += gridDim.x * blockDim.x) {
        unsigned k = g_keys[i];
        bool ok = (shift == 24) || ((k >> (shift + 8)) == (pfx >> (shift + 8)));
        if (ok) atomicAdd(&sh[(k >> shift) & 255u], 1u);
    }
    __syncthreads();
    if (threadIdx.x < 256 && sh[threadIdx.x])
        atomicAdd(&g_hist[threadIdx.x], sh[threadIdx.x]);
}

__global__ void select_kernel(int shift) {
    if (threadIdx.x == 0) {
        int rem = g_remaining;
        unsigned cum = 0;
        for (int b = 255; b >= 0; b--) {
            unsigned h = g_hist[b];
            if (cum + h >= (unsigned)rem) {
                g_prefix |= ((unsigned)b) << shift;
                g_remaining = rem - (int)cum;
                break;
            }
            cum += h;
        }
    }
    __syncthreads();
    if (threadIdx.x < 256) g_hist[threadIdx.x] = 0;
}

__global__ void compact_kernel() {
    unsigned T = g_prefix;
    for (int i = blockIdx.x * blockDim.x + threadIdx.x; i < NANCH;
         i += gridDim.x * blockDim.x) {
        unsigned k = g_keys[i];
        if (k >= T) {
            int p = atomicAdd(&g_candCount, 1);
            if (p < CAND_MAX)
                g_cand[p] = ((unsigned long long)k << 32) | (unsigned)(~i);
        }
    }
}

// ---------------- bitonic sort of candidates (key desc, idx asc) ----------------
__global__ void sort_kernel() {
    extern __shared__ unsigned long long s[];
    int tid = threadIdx.x;
    int cnt = g_candCount;
    if (cnt > CAND_MAX) cnt = CAND_MAX;
    for (int i = tid; i < CAND_MAX; i += blockDim.x)
        s[i] = (i < cnt) ? g_cand[i] : 0ULL;
    __syncthreads();
    for (int k = 2; k <= CAND_MAX; k <<= 1) {
        for (int j = k >> 1; j > 0; j >>= 1) {
            for (int i = tid; i < CAND_MAX; i += blockDim.x) {
                int ixj = i ^ j;
                if (ixj > i) {
                    unsigned long long a = s[i], b = s[ixj];
                    bool desc = ((i & k) == 0);
                    if (desc ? (a < b) : (a > b)) { s[i] = b; s[ixj] = a; }
                }
            }
            __syncthreads();
        }
    }
    for (int i = tid; i < PRE_NMS; i += blockDim.x) {
        unsigned long long e = s[i];
        unsigned idx = ~(unsigned)(e & 0xffffffffu);
        unsigned key = (unsigned)(e >> 32);
        unsigned bits = (key & 0x80000000u) ? (key ^ 0x80000000u) : ~key;
        g_selIdx[i] = (int)idx;
        g_selScore[i] = __uint_as_float(bits);
    }
}

// ---------------- decode + clip only selected 6000 ----------------
__global__ void decode_kernel(const float* __restrict__ im_info) {
    int i = blockIdx.x * blockDim.x + threadIdx.x;
    if (i >= PRE_NMS) return;
    int idx = g_selIdx[i];
    int l = 0;
    while (l < 4 && idx >= c_aoff[l + 1]) l++;
    int local = idx - c_aoff[l];
    int p = local / 3, a = local - p * 3;
    int W = c_W[l];
    int y = p / W, x = p - y * W;
    float stride = (float)c_stride[l];
    float cb = (stride - 1.f) * 0.5f;
    float ws = c_ws0[l * 3 + a] * 8.f, hs = c_hs0[l * 3 + a] * 8.f;
    float sx = x * stride, sy = y * stride;
    float ax1 = sx + cb - 0.5f * (ws - 1.f);
    float ay1 = sy + cb - 0.5f * (hs - 1.f);
    float ax2 = sx + cb + 0.5f * (ws - 1.f);
    float ay2 = sy + cb + 0.5f * (hs - 1.f);
    float w = ax2 - ax1 + 1.f, h = ay2 - ay1 + 1.f;
    float cx = ax1 + 0.5f * w, cy = ay1 + 0.5f * h;
    const float* dd = g_deltas + (size_t)idx * 4;
    float pcx = dd[0] * w + cx;
    float pcy = dd[1] * h + cy;
    float pw = expf(dd[2]) * w;
    float ph = expf(dd[3]) * h;
    float imW = im_info[1] - 1.f, imH = im_info[0] - 1.f;
    g_boxes[i * 4 + 0] = fminf(fmaxf(pcx - 0.5f * pw, 0.f), imW);
    g_boxes[i * 4 + 1] = fminf(fmaxf(pcy - 0.5f * ph, 0.f), imH);
    g_boxes[i * 4 + 2] = fminf(fmaxf(pcx + 0.5f * pw, 0.f), imW);
    g_boxes[i * 4 + 3] = fminf(fmaxf(pcy + 0.5f * ph, 0.f), imH);
}

// ---------------- IoU suppression bitmask ----------------
__global__ void iou_kernel() {
    int t = blockIdx.x * blockDim.x + threadIdx.x;
    if (t >= PRE_NMS * NWORDS) return;
    int i = t / NWORDS, wb = t - i * NWORDS;
    float bx1 = g_boxes[i * 4], by1 = g_boxes[i * 4 + 1];
    float bx2 = g_boxes[i * 4 + 2], by2 = g_boxes[i * 4 + 3];
    float areaI = (bx2 - bx1 + 1.f) * (by2 - by1 + 1.f);
    unsigned long long m = 0;
    int j0 = wb * 64;
    int jend = PRE_NMS - j0; if (jend > 64) jend = 64;
    for (int jj = 0; jj < jend; jj++) {
        int j = j0 + jj;
        float x1 = g_boxes[j * 4], y1 = g_boxes[j * 4 + 1];
        float x2 = g_boxes[j * 4 + 2], y2 = g_boxes[j * 4 + 3];
        float areaJ = (x2 - x1 + 1.f) * (y2 - y1 + 1.f);
        float iw = fminf(bx2, x2) - fmaxf(bx1, x1) + 1.f;
        float ih = fminf(by2, y2) - fmaxf(by1, y1) + 1.f;
        iw = fmaxf(iw, 0.f); ih = fmaxf(ih, 0.f);
        float inter = iw * ih;
        float iou = inter / (areaJ + areaI - inter);
        if (iou > NMS_TH) m |= (1ULL << jj);
    }
    g_iou[(size_t)i * NWORDS + wb] = m;
}

// ---------------- single-warp greedy NMS (rem words in registers) ----------------
__global__ void nms_kernel() {
    int lane = threadIdx.x;
    unsigned long long rem0 = 0, rem1 = 0, rem2 = 0;
    int w2 = lane + 64;
    if (w2 == 93) rem2 = ~((1ULL << 48) - 1ULL);   // bits 6000..6015 invalid
    else if (w2 > 93) rem2 = ~0ULL;                // words 94,95 nonexistent
    int nk = 0;
    while (nk < POST_NMS) {
        unsigned long long a0 = ~rem0, a1 = ~rem1, a2 = ~rem2;
        unsigned b0 = __ballot_sync(0xffffffffu, a0 != 0ULL);
        unsigned b1 = __ballot_sync(0xffffffffu, a1 != 0ULL);
        unsigned b2 = __ballot_sync(0xffffffffu, a2 != 0ULL);
        int slot, src;
        if (b0) { slot = 0; src = __ffs(b0) - 1; }
        else if (b1) { slot = 1; src = __ffs(b1) - 1; }
        else if (b2) { slot = 2; src = __ffs(b2) - 1; }
        else break;
        unsigned long long mysel = (slot == 0) ? a0 : ((slot == 1) ? a1 : a2);
        int mybit = __ffsll((long long)mysel) - 1;
        int bit = __shfl_sync(0xffffffffu, mybit, src);
        int idx = (slot * 32 + src) * 64 + bit;
        if (lane == 0) g_keep[nk] = idx;
        nk++;
        const unsigned long long* row = g_iou + (size_t)idx * NWORDS;
        unsigned long long r0 = __ldg(row + lane);
        unsigned long long r1 = __ldg(row + lane + 32);
        unsigned long long r2 = (w2 < NWORDS) ? __ldg(row + w2) : 0ULL;
        rem0 |= r0; rem1 |= r1; rem2 |= r2;
    }
    if (lane == 0) g_numKeep = nk;
}

// ---------------- assemble output (1000 x 6) ----------------
__global__ void output_kernel(float* __restrict__ out) {
    int i = blockIdx.x * blockDim.x + threadIdx.x;
    if (i >= POST_NMS) return;
    float x1 = 0, y1 = 0, x2 = 0, y2 = 0, s = 0;
    int nk = g_numKeep;
    if (i < nk) {
        int k = g_keep[i];
        x1 = g_boxes[k * 4 + 0]; y1 = g_boxes[k * 4 + 1];
        x2 = g_boxes[k * 4 + 2]; y2 = g_boxes[k * 4 + 3];
        s = g_selScore[k];
    }
    out[i * 6 + 0] = 0.f;
    out[i * 6 + 1] = x1;
    out[i * 6 + 2] = y1;
    out[i * 6 + 3] = x2;
    out[i * 6 + 4] = y2;
    out[i * 6 + 5] = s;
}

// ---------------- launch ----------------
extern "C" void kernel_launch(void* const* d_in, const int* in_sizes, int n_in,
                              void* d_out, int out_size) {
    const float* feats[5];
    for (int i = 0; i < 5; i++) feats[i] = (const float*)d_in[i];
    const float* im_info = (const float*)d_in[5];
    const float* convW = (const float*)d_in[6];
    const float* convB = (const float*)d_in[7];
    const float* sw = (const float*)d_in[8];
    const float* sb = (const float*)d_in[9];
    const float* bw = (const float*)d_in[10];
    const float* bb = (const float*)d_in[11];
    float* out = (float*)d_out;

    static const int Hs[5] = {128, 64, 32, 16, 8};
    static const int Ws[5] = {208, 104, 52, 26, 13};
    static const int pixBase[5] = {0, 26624, 33280, 34944, 35360};

    static bool attrDone = false;
    if (!attrDone) {
        cudaFuncSetAttribute(sort_kernel,
                             cudaFuncAttributeMaxDynamicSharedMemorySize, CAND_MAX * 8);
        cudaFuncSetAttribute(approx_score_kernel,
                             cudaFuncAttributeMaxDynamicSharedMemorySize, 2304 * 8 * 4);
        attrDone = true;
    }

    for (int l = 0; l < 5; l++) {
        int HW = Hs[l] * Ws[l];
        dim3 grid((HW + 31) / 32, 8);
        prep_kernel<<<grid, dim3(32, 32)>>>(feats[l], HW, pixBase[l]);
    }
    repackw_kernel<<<(512 * 2304 + 255) / 256, 256>>>(convW);
    fold_kernel<<<(2304 * 6 + 255) / 256, 256>>>(sw, sb, convB);
    approx_score_kernel<<<(NPIX + 7) / 8, 256, 2304 * 8 * 4>>>();

    const int shifts[4] = {24, 16, 8, 0};
    // pass 1: approx top-POOL_K threshold -> pool pixels
    reset_kernel<<<1, 256>>>(POOL_K);
    for (int s = 0; s < 4; s++) {
        hist_kernel<<<416, 256>>>(shifts[s]);
        select_kernel<<<1, 256>>>(shifts[s]);
    }
    zero_flags_kernel<<<(NPIX + 255) / 256, 256>>>();
    mark_compact_kernel<<<416, 256>>>();
    // exact recompute of pool pixels (R1-identical numerics)
    exact_conv_kernel<<<dim3(256, 8), 256>>>(convB);
    heads_pool_kernel<<<POOLMAX * 32 / 256, 256>>>(sw, sb, bw, bb);
    // pass 2: exact top-PRE_NMS
    reset_kernel<<<1, 256>>>(PRE_NMS);
    for (int s = 0; s < 4; s++) {
        hist_kernel<<<416, 256>>>(shifts[s]);
        select_kernel<<<1, 256>>>(shifts[s]);
    }
    compact_kernel<<<416, 256>>>();
    sort_kernel<<<1, 1024, CAND_MAX * 8>>>();
    decode_kernel<<<(PRE_NMS + 255) / 256, 256>>>(im_info);
    iou_kernel<<<(PRE_NMS * NWORDS + 255) / 256, 256>>>();
    nms_kernel<<<1, 32>>>();
    output_kernel<<<(POST_NMS + 255) / 256, 256>>>(out);
}

// round 9
// speedup vs baseline: 2.2260x; 1.4627x over previous
#include <cuda_runtime.h>
#include <math.h>
#include <stdint.h>

#define NPIX 35464
#define NANCH 106392
#define PRE_NMS 6000
#define POOL_K 6656
#define POOLMAX 8192
#define POST_NMS 1000
#define NMS_TH 0.7f
#define CAND_MAX 8192
#define NWORDS 94    // ceil(6000/64)

// ---------------- device scratch ----------------
__device__ float g_f[(size_t)NPIX * 512];     // exact features (pool pixels only)
__device__ float g_fp[(size_t)NPIX * 256];    // fp32 input, pixel-major
__device__ float g_wT[2304 * 512];            // fp32 conv weights [k][oc]
__device__ float g_weff[2304 * 6];            // folded conv+score weights [k][ch]
__device__ float g_weffB[6];                  // folded bias
__device__ unsigned g_keys[NANCH];
__device__ float g_deltas[(size_t)NANCH * 4];
__device__ unsigned g_hist[256];
__device__ unsigned g_prefix;
__device__ int g_remaining;
__device__ int g_candCount;
__device__ unsigned long long g_cand[CAND_MAX];
__device__ int g_pixFlag[NPIX];
__device__ int g_poolPix[POOLMAX];
__device__ int g_poolCnt;
__device__ int g_selIdx[PRE_NMS];
__device__ float g_selScore[PRE_NMS];
__device__ float g_boxes[PRE_NMS * 4];
__device__ unsigned long long g_iou[(size_t)PRE_NMS * NWORDS];
__device__ int g_keep[POST_NMS];
__device__ int g_numKeep;

// constants
__constant__ int c_aoff[6] = {0, 79872, 99840, 104832, 106080, 106392};
__constant__ int c_W[5] = {208, 104, 52, 26, 13};
__constant__ int c_H[5] = {128, 64, 32, 16, 8};
__constant__ int c_stride[5] = {4, 8, 16, 32, 64};
__constant__ int c_pixBase[5] = {0, 26624, 33280, 34944, 35360};
__constant__ int c_ws0[15] = {6,4,3, 11,8,6, 23,16,11, 45,32,23, 91,64,45};
__constant__ int c_hs0[15] = {3,4,6, 6,8,12, 12,16,22, 22,32,46, 46,64,90};

// ---------------- prep (all 5 levels fused): NCHW fp32 -> pixel-major fp32 ----------------
__global__ void prep_kernel(const float* __restrict__ p2, const float* __restrict__ p3,
                            const float* __restrict__ p4, const float* __restrict__ p5,
                            const float* __restrict__ p6) {
    __shared__ float sh[32][33];
    int g0 = blockIdx.x * 32;
    int l = 0;
    while (l < 4 && g0 >= c_pixBase[l + 1]) l++;
    const float* f = (l == 0) ? p2 : (l == 1) ? p3 : (l == 2) ? p4 : (l == 3) ? p5 : p6;
    int HW = c_W[l] * c_H[l];
    int base = c_pixBase[l];
    int ic0 = blockIdx.y * 32;
    int tx = threadIdx.x, ty = threadIdx.y;
    int p = g0 - base + tx;
    sh[ty][tx] = (p < HW) ? f[(size_t)(ic0 + ty) * HW + p] : 0.f;
    __syncthreads();
    int pw = g0 - base + ty;
    if (pw < HW)
        g_fp[(size_t)(base + pw) * 256 + ic0 + tx] = sh[tx][ty];
}

// ---------------- weight transpose: [oc][ic][3][3] -> [k][oc], k=tap*256+ic ----------------
__global__ void repackw_kernel(const float* __restrict__ w) {
    int t = blockIdx.x * blockDim.x + threadIdx.x;
    if (t >= 512 * 2304) return;
    int oc = t / 2304, k = t - oc * 2304;
    int tap = k >> 8, ic = k & 255;
    g_wT[k * 512 + oc] = w[oc * 2304 + ic * 9 + tap];
}

// ---------------- fold score head into conv: W_eff[k][ch], bias ----------------
__global__ void fold_kernel(const float* __restrict__ sw, const float* __restrict__ sb,
                            const float* __restrict__ convB) {
    int t = blockIdx.x * blockDim.x + threadIdx.x;
    if (t < 6) {
        float acc = sb[t];
        for (int oc = 0; oc < 512; oc++) acc += sw[t * 512 + oc] * convB[oc];
        g_weffB[t] = acc;
    }
    if (t >= 2304 * 6) return;
    int k = t / 6, ch = t - k * 6;
    const float4* wr = (const float4*)(g_wT + (size_t)k * 512);
    const float4* sr = (const float4*)(sw + ch * 512);
    float acc = 0.f;
#pragma unroll 4
    for (int q = 0; q < 128; q++) {
        float4 a = wr[q], b = sr[q];
        acc += a.x * b.x + a.y * b.y + a.z * b.z + a.w * b.w;
    }
    g_weff[t] = acc;
}

// ---------------- approx scores: folded 3x3x256 -> 6 logits, warp per 4 pixels ----------------
__global__ void __launch_bounds__(256) approx_score_kernel() {
    extern __shared__ float s_w[];   // [2304][8] padded
    __shared__ float s_wb[6];
    int tid = threadIdx.x;
    for (int i = tid; i < 2304 * 6; i += 256) {
        int k = i / 6, ch = i - k * 6;
        s_w[k * 8 + ch] = g_weff[i];
    }
    if (tid < 6) s_wb[tid] = g_weffB[tid];
    __syncthreads();
    int lane = tid & 31;
    const int ic0 = lane * 8;
    for (int p = 0; p < 4; p++) {
        int gw = blockIdx.x * 32 + (tid >> 5) * 4 + p;
        if (gw >= NPIX) break;
        int l = 0;
        while (l < 4 && gw >= c_pixBase[l + 1]) l++;
        const int Wl = c_W[l], Hl = c_H[l];
        int local = gw - c_pixBase[l];
        int py = local / Wl, px = local - py * Wl;
        float acc[6] = {0.f, 0.f, 0.f, 0.f, 0.f, 0.f};
#pragma unroll
        for (int tap = 0; tap < 9; tap++) {
            int dy = tap / 3 - 1, dx = tap % 3 - 1;
            int iy = py + dy, ix = px + dx;
            if ((unsigned)iy >= (unsigned)Hl || (unsigned)ix >= (unsigned)Wl) continue;
            const float* src = g_fp + ((size_t)(c_pixBase[l] + iy * Wl + ix)) * 256 + ic0;
            float4 v0 = *(const float4*)src;
            float4 v1 = *(const float4*)(src + 4);
            float a[8] = {v0.x, v0.y, v0.z, v0.w, v1.x, v1.y, v1.z, v1.w};
            const float* wp = s_w + (size_t)(tap * 256 + ic0) * 8;
#pragma unroll
            for (int j = 0; j < 8; j++) {
                float4 w0 = *(const float4*)(wp + j * 8);
                float2 w1 = *(const float2*)(wp + j * 8 + 4);
                acc[0] += a[j] * w0.x; acc[1] += a[j] * w0.y; acc[2] += a[j] * w0.z;
                acc[3] += a[j] * w0.w; acc[4] += a[j] * w1.x; acc[5] += a[j] * w1.y;
            }
        }
#pragma unroll
        for (int ch = 0; ch < 6; ch++)
#pragma unroll
            for (int off = 16; off; off >>= 1)
                acc[ch] += __shfl_xor_sync(0xffffffffu, acc[ch], off);
        if (lane < 3) {
            float cb = acc[lane] + s_wb[lane];
            float cf = acc[3 + lane] + s_wb[3 + lane];
            float s = 1.f / (1.f + expf(cb - cf));
            unsigned bits = __float_as_uint(s);
            unsigned key = bits ^ ((unsigned)((int)bits >> 31) | 0x80000000u);
            g_keys[gw * 3 + lane] = key;
        }
    }
}

// ---------------- pool marking ----------------
__global__ void zero_flags_kernel() {
    int i = blockIdx.x * blockDim.x + threadIdx.x;
    if (i < NPIX) g_pixFlag[i] = 0;
    if (i == 0) g_poolCnt = 0;
}

__global__ void mark_compact_kernel() {
    unsigned T = g_prefix;
    for (int i = blockIdx.x * blockDim.x + threadIdx.x; i < NANCH;
         i += gridDim.x * blockDim.x) {
        if (g_keys[i] >= T) {
            int pix = i / 3;
            if (atomicExch(&g_pixFlag[pix], 1) == 0) {
                int p = atomicAdd(&g_poolCnt, 1);
                if (p < POOLMAX) g_poolPix[p] = pix;
            }
        }
    }
}

// ---------------- exact fp32 recompute of pool pixels (R1-identical chain) ----------------
// grid (256, 2), 256 threads. Tile: 32 pixels x 256 oc. Thread: 4 px x 8 oc.
__global__ void __launch_bounds__(256) exact_conv_kernel(const float* __restrict__ bias) {
    __shared__ float sA[32][33];
    __shared__ float sW[32][264];
    __shared__ int s_pix[32], s_base[32], s_W[32], s_H[32], s_py[32], s_px[32];

    const int tid = threadIdx.x;
    const int cnt = g_poolCnt < POOLMAX ? g_poolCnt : POOLMAX;
    const int ptile = blockIdx.x;
    if (ptile * 32 >= cnt) return;
    const int oc0 = blockIdx.y * 256;

    if (tid < 32) {
        int idx = ptile * 32 + tid;
        int pix = (idx < cnt) ? g_poolPix[idx] : -1;
        s_pix[tid] = pix;
        if (pix >= 0) {
            int l = 0;
            while (l < 4 && pix >= c_pixBase[l + 1]) l++;
            int local = pix - c_pixBase[l];
            int Wl = c_W[l];
            s_base[tid] = c_pixBase[l];
            s_W[tid] = Wl;
            s_H[tid] = c_H[l];
            s_py[tid] = local / Wl;
            s_px[tid] = local - (local / Wl) * Wl;
        }
    }
    __syncthreads();

    const int lane = tid & 31, wid = tid >> 5;
    const int ocL = wid * 32 + (lane >> 3) * 8;   // 0..255 step 8
    const int p0 = (lane & 7) * 4;                // 4 pixels

    const int ap = tid >> 3;            // pixel slot for A loads
    const int akq = (tid & 7) * 4;      // ic sub-offset for A loads
    const int wkk = tid >> 6;           // k sub-row for W loads (0..3)
    const int woc = (tid & 63) * 4;     // oc for W loads

    float acc[4][8];
#pragma unroll
    for (int i = 0; i < 4; i++)
#pragma unroll
        for (int j = 0; j < 8; j++) acc[i][j] = 0.f;

    for (int chunk = 0; chunk < 72; chunk++) {
        const int tap = chunk >> 3;
        const int ic0 = (chunk & 7) * 32;
        const int dy = tap / 3 - 1;
        const int dx = tap - (tap / 3) * 3 - 1;
        const int k0 = chunk * 32;
        // A: 32 pixels x 32 ic
        {
            float4 val = make_float4(0.f, 0.f, 0.f, 0.f);
            int pix = s_pix[ap];
            if (pix >= 0) {
                int iy = s_py[ap] + dy, ix = s_px[ap] + dx;
                if ((unsigned)iy < (unsigned)s_H[ap] && (unsigned)ix < (unsigned)s_W[ap]) {
                    int np = s_base[ap] + iy * s_W[ap] + ix;
                    val = *(const float4*)(g_fp + (size_t)np * 256 + ic0 + akq);
                }
            }
            sA[ap][akq + 0] = val.x;
            sA[ap][akq + 1] = val.y;
            sA[ap][akq + 2] = val.z;
            sA[ap][akq + 3] = val.w;
        }
        // W: 32 k x 256 oc
#pragma unroll
        for (int r = 0; r < 8; r++) {
            int kk = r * 4 + wkk;
            *(float4*)&sW[kk][woc] =
                *(const float4*)(g_wT + (size_t)(k0 + kk) * 512 + oc0 + woc);
        }
        __syncthreads();
#pragma unroll 8
        for (int kk = 0; kk < 32; kk++) {
            float a0 = sA[p0 + 0][kk];
            float a1 = sA[p0 + 1][kk];
            float a2 = sA[p0 + 2][kk];
            float a3 = sA[p0 + 3][kk];
#pragma unroll
            for (int j = 0; j < 8; j++) {
                float w = sW[kk][ocL + j];
                acc[0][j] = fmaf(a0, w, acc[0][j]);
                acc[1][j] = fmaf(a1, w, acc[1][j]);
                acc[2][j] = fmaf(a2, w, acc[2][j]);
                acc[3][j] = fmaf(a3, w, acc[3][j]);
            }
        }
        __syncthreads();
    }

#pragma unroll
    for (int i = 0; i < 4; i++) {
        int pix = s_pix[p0 + i];
        if (pix >= 0) {
            float* o = g_f + (size_t)pix * 512 + oc0 + ocL;
#pragma unroll
            for (int j = 0; j < 8; j++) o[j] = acc[i][j] + bias[oc0 + ocL + j];
        }
    }
}

// ---------------- exact heads on pool pixels (R1-identical) ----------------
__device__ __forceinline__ void heads_pixel(int gw, int lane,
        const float* __restrict__ sw, const float* __restrict__ sb,
        const float* __restrict__ bw, const float* __restrict__ bb)
{
    const float* f = g_f + (size_t)gw * 512;
    float4 v[4];
#pragma unroll
    for (int j = 0; j < 4; j++)
        v[j] = *(const float4*)(f + j * 128 + lane * 4);

    float c[6];
#pragma unroll
    for (int ch = 0; ch < 6; ch++) {
        const float* w = sw + ch * 512;
        float s = 0.f;
#pragma unroll
        for (int j = 0; j < 4; j++) {
            float4 ww = *(const float4*)(w + j * 128 + lane * 4);
            s += v[j].x * ww.x + v[j].y * ww.y + v[j].z * ww.z + v[j].w * ww.w;
        }
#pragma unroll
        for (int off = 16; off; off >>= 1) s += __shfl_xor_sync(0xffffffffu, s, off);
        c[ch] = s + sb[ch];
    }
    float d[12];
#pragma unroll
    for (int ch = 0; ch < 12; ch++) {
        const float* w = bw + ch * 512;
        float s = 0.f;
#pragma unroll
        for (int j = 0; j < 4; j++) {
            float4 ww = *(const float4*)(w + j * 128 + lane * 4);
            s += v[j].x * ww.x + v[j].y * ww.y + v[j].z * ww.z + v[j].w * ww.w;
        }
#pragma unroll
        for (int off = 16; off; off >>= 1) s += __shfl_xor_sync(0xffffffffu, s, off);
        d[ch] = s + bb[ch];
    }
    int base = gw * 3;
    if (lane < 3) {
        float s = 1.f / (1.f + expf(c[lane] - c[3 + lane]));
        unsigned bits = __float_as_uint(s);
        unsigned key = bits ^ ((unsigned)((int)bits >> 31) | 0x80000000u);
        g_keys[base + lane] = key;
    }
    if (lane < 12) {
        g_deltas[(size_t)base * 4 + lane] = d[lane];
    }
}

__global__ void heads_pool_kernel(const float* __restrict__ sw, const float* __restrict__ sb,
                                  const float* __restrict__ bw, const float* __restrict__ bb)
{
    int i = (blockIdx.x * blockDim.x + threadIdx.x) >> 5;
    int lane = threadIdx.x & 31;
    if (i >= g_poolCnt) return;
    heads_pixel(g_poolPix[i], lane, sw, sb, bw, bb);
}

// ---------------- radix top-k threshold selection ----------------
__global__ void reset_kernel(int k) {
    int t = threadIdx.x;
    if (t < 256) g_hist[t] = 0;
    if (t == 0) { g_prefix = 0; g_remaining = k; g_candCount = 0; g_numKeep = 0; }
}

__global__ void hist_kernel(int shift) {
    __shared__ unsigned sh[256];
    if (threadIdx.x < 256) sh[threadIdx.x] = 0;
    __syncthreads();
    unsigned pfx = g_prefix;
    for (int i = blockIdx.x * blockDim.x + threadIdx.x; i < NANCH;
         i += gridDim.x * blockDim.x) {
        unsigned k = g_keys[i];
        bool ok = (shift == 24) || ((k >> (shift + 8)) == (pfx >> (shift + 8)));
        if (ok) atomicAdd(&sh[(k >> shift) & 255u], 1u);
    }
    __syncthreads();
    if (threadIdx.x < 256 && sh[threadIdx.x])
        atomicAdd(&g_hist[threadIdx.x], sh[threadIdx.x]);
}

// parallel select: 256-thread suffix scan; same semantics as serial walk-down
__global__ void select_kernel(int shift) {
    __shared__ unsigned suf[256];
    int t = threadIdx.x;
    unsigned h = g_hist[t];
    suf[t] = h;
    __syncthreads();
    for (int d = 1; d < 256; d <<= 1) {
        unsigned v = (t + d < 256) ? suf[t + d] : 0u;
        __syncthreads();
        suf[t] += v;
        __syncthreads();
    }
    unsigned rem = (unsigned)g_remaining;
    unsigned S = suf[t];
    unsigned Snext = (t < 255) ? suf[t + 1] : 0u;
    if (S >= rem && Snext < rem) {
        g_prefix |= ((unsigned)t) << shift;
        g_remaining = (int)(rem - (S - h));
    }
    g_hist[t] = 0;
}

__global__ void compact_kernel() {
    unsigned T = g_prefix;
    for (int i = blockIdx.x * blockDim.x + threadIdx.x; i < NANCH;
         i += gridDim.x * blockDim.x) {
        unsigned k = g_keys[i];
        if (k >= T) {
            int p = atomicAdd(&g_candCount, 1);
            if (p < CAND_MAX)
                g_cand[p] = ((unsigned long long)k << 32) | (unsigned)(~i);
        }
    }
}

// ---------------- bitonic sort of candidates (key desc, idx asc) ----------------
__global__ void sort_kernel() {
    extern __shared__ unsigned long long s[];
    int tid = threadIdx.x;
    int cnt = g_candCount;
    if (cnt > CAND_MAX) cnt = CAND_MAX;
    for (int i = tid; i < CAND_MAX; i += blockDim.x)
        s[i] = (i < cnt) ? g_cand[i] : 0ULL;
    __syncthreads();
    for (int k = 2; k <= CAND_MAX; k <<= 1) {
        for (int j = k >> 1; j > 0; j >>= 1) {
            for (int i = tid; i < CAND_MAX; i += blockDim.x) {
                int ixj = i ^ j;
                if (ixj > i) {
                    unsigned long long a = s[i], b = s[ixj];
                    bool desc = ((i & k) == 0);
                    if (desc ? (a < b) : (a > b)) { s[i] = b; s[ixj] = a; }
                }
            }
            __syncthreads();
        }
    }
    for (int i = tid; i < PRE_NMS; i += blockDim.x) {
        unsigned long long e = s[i];
        unsigned idx = ~(unsigned)(e & 0xffffffffu);
        unsigned key = (unsigned)(e >> 32);
        unsigned bits = (key & 0x80000000u) ? (key ^ 0x80000000u) : ~key;
        g_selIdx[i] = (int)idx;
        g_selScore[i] = __uint_as_float(bits);
    }
}

// ---------------- decode + clip only selected 6000 ----------------
__global__ void decode_kernel(const float* __restrict__ im_info) {
    int i = blockIdx.x * blockDim.x + threadIdx.x;
    if (i >= PRE_NMS) return;
    int idx = g_selIdx[i];
    int l = 0;
    while (l < 4 && idx >= c_aoff[l + 1]) l++;
    int local = idx - c_aoff[l];
    int p = local / 3, a = local - p * 3;
    int W = c_W[l];
    int y = p / W, x = p - y * W;
    float stride = (float)c_stride[l];
    float cb = (stride - 1.f) * 0.5f;
    float ws = c_ws0[l * 3 + a] * 8.f, hs = c_hs0[l * 3 + a] * 8.f;
    float sx = x * stride, sy = y * stride;
    float ax1 = sx + cb - 0.5f * (ws - 1.f);
    float ay1 = sy + cb - 0.5f * (hs - 1.f);
    float ax2 = sx + cb + 0.5f * (ws - 1.f);
    float ay2 = sy + cb + 0.5f * (hs - 1.f);
    float w = ax2 - ax1 + 1.f, h = ay2 - ay1 + 1.f;
    float cx = ax1 + 0.5f * w, cy = ay1 + 0.5f * h;
    const float* dd = g_deltas + (size_t)idx * 4;
    float pcx = dd[0] * w + cx;
    float pcy = dd[1] * h + cy;
    float pw = expf(dd[2]) * w;
    float ph = expf(dd[3]) * h;
    float imW = im_info[1] - 1.f, imH = im_info[0] - 1.f;
    g_boxes[i * 4 + 0] = fminf(fmaxf(pcx - 0.5f * pw, 0.f), imW);
    g_boxes[i * 4 + 1] = fminf(fmaxf(pcy - 0.5f * ph, 0.f), imH);
    g_boxes[i * 4 + 2] = fminf(fmaxf(pcx + 0.5f * pw, 0.f), imW);
    g_boxes[i * 4 + 3] = fminf(fmaxf(pcy + 0.5f * ph, 0.f), imH);
}

// ---------------- IoU suppression bitmask (smem-tiled) ----------------
// grid (94, 94): blockIdx.x = i-tile (64 rows), blockIdx.y = word column. 64 threads.
__global__ void iou_kernel() {
    __shared__ float4 sj[64];
    int wb = blockIdx.y;
    int t = threadIdx.x;
    int j0 = wb * 64;
    {
        int j = j0 + t;
        sj[t] = (j < PRE_NMS) ? ((const float4*)g_boxes)[j]
                              : make_float4(0.f, 0.f, 0.f, 0.f);
    }
    __syncthreads();
    int i = blockIdx.x * 64 + t;
    if (i >= PRE_NMS) return;
    float4 bi = ((const float4*)g_boxes)[i];
    float areaI = (bi.z - bi.x + 1.f) * (bi.w - bi.y + 1.f);
    unsigned long long m = 0;
    int jend = PRE_NMS - j0; if (jend > 64) jend = 64;
    for (int jj = 0; jj < jend; jj++) {
        float4 bj = sj[jj];
        float areaJ = (bj.z - bj.x + 1.f) * (bj.w - bj.y + 1.f);
        float iw = fminf(bi.z, bj.z) - fmaxf(bi.x, bj.x) + 1.f;
        float ih = fminf(bi.w, bj.w) - fmaxf(bi.y, bj.y) + 1.f;
        iw = fmaxf(iw, 0.f); ih = fmaxf(ih, 0.f);
        float inter = iw * ih;
        float iou = inter / (areaJ + areaI - inter);
        if (iou > NMS_TH) m |= (1ULL << jj);
    }
    g_iou[(size_t)i * NWORDS + wb] = m;
}

// ---------------- single-warp greedy NMS with 4-way row prefetch ----------------
__global__ void nms_kernel() {
    int lane = threadIdx.x;
    unsigned long long rem0 = 0, rem1 = 0, rem2 = 0;
    int w2 = lane + 64;
    if (w2 == 93) rem2 = ~((1ULL << 48) - 1ULL);
    else if (w2 > 93) rem2 = ~0ULL;
    int nk = 0;
    while (nk < POST_NMS) {
        unsigned long long a0 = ~rem0, a1 = ~rem1, a2 = ~rem2;
        int cand[4] = {-1, -1, -1, -1};
#pragma unroll
        for (int t = 0; t < 4; t++) {
            unsigned b0 = __ballot_sync(0xffffffffu, a0 != 0ULL);
            unsigned b1 = __ballot_sync(0xffffffffu, a1 != 0ULL);
            unsigned b2 = __ballot_sync(0xffffffffu, a2 != 0ULL);
            int slot = -1, src = 0;
            if (b0) { slot = 0; src = __ffs(b0) - 1; }
            else if (b1) { slot = 1; src = __ffs(b1) - 1; }
            else if (b2) { slot = 2; src = __ffs(b2) - 1; }
            if (slot < 0) break;
            unsigned long long mysel = (slot == 0) ? a0 : ((slot == 1) ? a1 : a2);
            int mybit = __ffsll((long long)mysel) - 1;
            int bit = __shfl_sync(0xffffffffu, mybit, src);
            cand[t] = (slot * 32 + src) * 64 + bit;
            if (lane == src) {
                if (slot == 0) a0 &= (a0 - 1);
                else if (slot == 1) a1 &= (a1 - 1);
                else a2 &= (a2 - 1);
            }
        }
        if (cand[0] < 0) break;
        unsigned long long r[4][3];
#pragma unroll
        for (int t = 0; t < 4; t++) {
            if (cand[t] >= 0) {
                const unsigned long long* row = g_iou + (size_t)cand[t] * NWORDS;
                r[t][0] = __ldg(row + lane);
                r[t][1] = __ldg(row + lane + 32);
                r[t][2] = (w2 < NWORDS) ? __ldg(row + w2) : 0ULL;
            } else {
                r[t][0] = r[t][1] = r[t][2] = 0ULL;
            }
        }
#pragma unroll
        for (int t = 0; t < 4; t++) {
            int idx = cand[t];
            if (idx < 0 || nk >= POST_NMS) break;
            if (t > 0) {
                int w = idx >> 6, b = idx & 63;
                unsigned long long mine = (w < 32) ? rem0 : ((w < 64) ? rem1 : rem2);
                unsigned long long ow = __shfl_sync(0xffffffffu, mine, w & 31);
                if ((ow >> b) & 1ULL) continue;   // suppressed by earlier keep this round
            }
            if (lane == 0) g_keep[nk] = idx;
            nk++;
            rem0 |= r[t][0]; rem1 |= r[t][1]; rem2 |= r[t][2];
        }
    }
    if (lane == 0) g_numKeep = nk;
}

// ---------------- assemble output (1000 x 6) ----------------
__global__ void output_kernel(float* __restrict__ out) {
    int i = blockIdx.x * blockDim.x + threadIdx.x;
    if (i >= POST_NMS) return;
    float x1 = 0, y1 = 0, x2 = 0, y2 = 0, s = 0;
    int nk = g_numKeep;
    if (i < nk) {
        int k = g_keep[i];
        x1 = g_boxes[k * 4 + 0]; y1 = g_boxes[k * 4 + 1];
        x2 = g_boxes[k * 4 + 2]; y2 = g_boxes[k * 4 + 3];
        s = g_selScore[k];
    }
    out[i * 6 + 0] = 0.f;
    out[i * 6 + 1] = x1;
    out[i * 6 + 2] = y1;
    out[i * 6 + 3] = x2;
    out[i * 6 + 4] = y2;
    out[i * 6 + 5] = s;
}

// ---------------- launch ----------------
extern "C" void kernel_launch(void* const* d_in, const int* in_sizes, int n_in,
                              void* d_out, int out_size) {
    const float* feats[5];
    for (int i = 0; i < 5; i++) feats[i] = (const float*)d_in[i];
    const float* im_info = (const float*)d_in[5];
    const float* convW = (const float*)d_in[6];
    const float* convB = (const float*)d_in[7];
    const float* sw = (const float*)d_in[8];
    const float* sb = (const float*)d_in[9];
    const float* bw = (const float*)d_in[10];
    const float* bb = (const float*)d_in[11];
    float* out = (float*)d_out;

    static bool attrDone = false;
    if (!attrDone) {
        cudaFuncSetAttribute(sort_kernel,
                             cudaFuncAttributeMaxDynamicSharedMemorySize, CAND_MAX * 8);
        cudaFuncSetAttribute(approx_score_kernel,
                             cudaFuncAttributeMaxDynamicSharedMemorySize, 2304 * 8 * 4);
        attrDone = true;
    }

    prep_kernel<<<dim3(1109, 8), dim3(32, 32)>>>(feats[0], feats[1], feats[2],
                                                 feats[3], feats[4]);
    repackw_kernel<<<(512 * 2304 + 255) / 256, 256>>>(convW);
    fold_kernel<<<(2304 * 6 + 255) / 256, 256>>>(sw, sb, convB);
    approx_score_kernel<<<1109, 256, 2304 * 8 * 4>>>();

    const int shifts[4] = {24, 16, 8, 0};
    // pass 1: approx top-POOL_K threshold -> pool pixels
    reset_kernel<<<1, 256>>>(POOL_K);
    for (int s = 0; s < 4; s++) {
        hist_kernel<<<416, 256>>>(shifts[s]);
        select_kernel<<<1, 256>>>(shifts[s]);
    }
    zero_flags_kernel<<<(NPIX + 255) / 256, 256>>>();
    mark_compact_kernel<<<416, 256>>>();
    // exact recompute of pool pixels (R1-identical numerics)
    exact_conv_kernel<<<dim3(256, 2), 256>>>(convB);
    heads_pool_kernel<<<POOLMAX * 32 / 256, 256>>>(sw, sb, bw, bb);
    // pass 2: exact top-PRE_NMS
    reset_kernel<<<1, 256>>>(PRE_NMS);
    for (int s = 0; s < 4; s++) {
        hist_kernel<<<416, 256>>>(shifts[s]);
        select_kernel<<<1, 256>>>(shifts[s]);
    }
    compact_kernel<<<416, 256>>>();
    sort_kernel<<<1, 1024, CAND_MAX * 8>>>();
    decode_kernel<<<(PRE_NMS + 255) / 256, 256>>>(im_info);
    iou_kernel<<<dim3(94, 94), 64>>>();
    nms_kernel<<<1, 32>>>();
    output_kernel<<<(POST_NMS + 255) / 256, 256>>>(out);
}

// round 11
// speedup vs baseline: 3.1162x; 1.3999x over previous
#include <cuda_runtime.h>
#include <math.h>
#include <stdint.h>

#define NPIX 35464
#define NANCH 106392
#define PRE_NMS 6000
#define POOL_K 6656
#define POOLMAX 8192
#define POST_NMS 1000
#define NMS_TH 0.7f
#define CAND_MAX 8192
#define NWORDS 94    // ceil(6000/64)

// ---------------- device scratch ----------------
__device__ float g_f[(size_t)NPIX * 512];     // exact features (pool pixels only)
__device__ float g_fp[(size_t)NPIX * 256];    // fp32 input, pixel-major
__device__ float g_wT[2304 * 512];            // fp32 conv weights [k][oc]
__device__ float g_wd[2304 * 3];              // folded diff weights [k][a]
__device__ float g_wdB[3];                    // folded diff bias
__device__ unsigned g_keys[NANCH];
__device__ float g_deltas[(size_t)NANCH * 4];
__device__ unsigned g_hist16[65536];
__device__ unsigned g_prefix;
__device__ int g_candCount;
__device__ unsigned long long g_cand[CAND_MAX];
__device__ int g_pixFlag[NPIX];
__device__ int g_poolPix[POOLMAX];
__device__ int g_poolCnt;
__device__ int g_selIdx[PRE_NMS];
__device__ float g_selScore[PRE_NMS];
__device__ float g_boxes[PRE_NMS * 4];
__device__ unsigned long long g_iou[(size_t)PRE_NMS * NWORDS];
__device__ int g_keep[POST_NMS];
__device__ int g_numKeep;

// constants
__constant__ int c_aoff[6] = {0, 79872, 99840, 104832, 106080, 106392};
__constant__ int c_W[5] = {208, 104, 52, 26, 13};
__constant__ int c_H[5] = {128, 64, 32, 16, 8};
__constant__ int c_stride[5] = {4, 8, 16, 32, 64};
__constant__ int c_pixBase[5] = {0, 26624, 33280, 34944, 35360};
__constant__ int c_ws0[15] = {6,4,3, 11,8,6, 23,16,11, 45,32,23, 91,64,45};
__constant__ int c_hs0[15] = {3,4,6, 6,8,12, 12,16,22, 22,32,46, 46,64,90};

// ---------------- prep (all 5 levels fused): NCHW fp32 -> pixel-major fp32 ----------------
__global__ void prep_kernel(const float* __restrict__ p2, const float* __restrict__ p3,
                            const float* __restrict__ p4, const float* __restrict__ p5,
                            const float* __restrict__ p6) {
    __shared__ float sh[32][33];
    int g0 = blockIdx.x * 32;
    int l = 0;
    while (l < 4 && g0 >= c_pixBase[l + 1]) l++;
    const float* f = (l == 0) ? p2 : (l == 1) ? p3 : (l == 2) ? p4 : (l == 3) ? p5 : p6;
    int HW = c_W[l] * c_H[l];
    int base = c_pixBase[l];
    int ic0 = blockIdx.y * 32;
    int tx = threadIdx.x, ty = threadIdx.y;
    int p = g0 - base + tx;
    sh[ty][tx] = (p < HW) ? f[(size_t)(ic0 + ty) * HW + p] : 0.f;
    __syncthreads();
    int pw = g0 - base + ty;
    if (pw < HW)
        g_fp[(size_t)(base + pw) * 256 + ic0 + tx] = sh[tx][ty];
}

// ---------------- weight transpose: [oc][ic][3][3] -> [k][oc], k=tap*256+ic ----------------
__global__ void repackw_kernel(const float* __restrict__ w) {
    int t = blockIdx.x * blockDim.x + threadIdx.x;
    if (t >= 512 * 2304) return;
    int oc = t / 2304, k = t - oc * 2304;
    int tap = k >> 8, ic = k & 255;
    g_wT[k * 512 + oc] = w[oc * 2304 + ic * 9 + tap];
}

// ---------------- fold score-diff head into conv: wd[k][a] = Weff[k][3+a]-Weff[k][a] ----------------
__global__ void fold_kernel(const float* __restrict__ sw, const float* __restrict__ sb,
                            const float* __restrict__ convB) {
    int t = blockIdx.x * blockDim.x + threadIdx.x;
    if (t < 3) {
        float acc = sb[3 + t] - sb[t];
        for (int oc = 0; oc < 512; oc++)
            acc += (sw[(3 + t) * 512 + oc] - sw[t * 512 + oc]) * convB[oc];
        g_wdB[t] = acc;
    }
    if (t >= 2304 * 3) return;
    int k = t / 3, a = t - k * 3;
    const float4* wr = (const float4*)(g_wT + (size_t)k * 512);
    const float4* s0 = (const float4*)(sw + a * 512);
    const float4* s1 = (const float4*)(sw + (3 + a) * 512);
    float acc = 0.f;
#pragma unroll 4
    for (int q = 0; q < 128; q++) {
        float4 wv = wr[q];
        float4 b0 = s0[q], b1 = s1[q];
        acc += wv.x * (b1.x - b0.x) + wv.y * (b1.y - b0.y)
             + wv.z * (b1.z - b0.z) + wv.w * (b1.w - b0.w);
    }
    g_wd[t] = acc;
}

// ---------------- approx scores: folded diff 3x3x256 -> 3 logit-diffs, warp per 4 px ----------------
// swizzled smem layout: addr(k) = k*4 + (k>>3)*4 floats -> conflict-free LDS.128
__global__ void __launch_bounds__(256) approx_score_kernel() {
    __shared__ float s_wd[2304 * 4 + 288 * 4];   // 41472 B
    __shared__ float s_bd[3];
    int tid = threadIdx.x;
    for (int k = tid; k < 2304; k += 256) {
        int base = k * 4 + (k >> 3) * 4;
        s_wd[base + 0] = g_wd[k * 3 + 0];
        s_wd[base + 1] = g_wd[k * 3 + 1];
        s_wd[base + 2] = g_wd[k * 3 + 2];
        s_wd[base + 3] = 0.f;
    }
    if (tid < 3) s_bd[tid] = g_wdB[tid];
    __syncthreads();
    int lane = tid & 31;
    const int ic0 = lane * 8;
    for (int p = 0; p < 4; p++) {
        int gw = blockIdx.x * 32 + (tid >> 5) * 4 + p;
        if (gw >= NPIX) break;
        int l = 0;
        while (l < 4 && gw >= c_pixBase[l + 1]) l++;
        const int Wl = c_W[l], Hl = c_H[l];
        int local = gw - c_pixBase[l];
        int py = local / Wl, px = local - py * Wl;
        float d0 = 0.f, d1 = 0.f, d2 = 0.f;
#pragma unroll
        for (int tap = 0; tap < 9; tap++) {
            int dy = tap / 3 - 1, dx = tap % 3 - 1;
            int iy = py + dy, ix = px + dx;
            if ((unsigned)iy >= (unsigned)Hl || (unsigned)ix >= (unsigned)Wl) continue;
            const float* src = g_fp + ((size_t)(c_pixBase[l] + iy * Wl + ix)) * 256 + ic0;
            float4 v0 = *(const float4*)src;
            float4 v1 = *(const float4*)(src + 4);
            float a[8] = {v0.x, v0.y, v0.z, v0.w, v1.x, v1.y, v1.z, v1.w};
            const float* wp = s_wd + tap * 1152 + lane * 36;
#pragma unroll
            for (int j = 0; j < 8; j++) {
                float4 wd = *(const float4*)(wp + j * 4);
                d0 = fmaf(a[j], wd.x, d0);
                d1 = fmaf(a[j], wd.y, d1);
                d2 = fmaf(a[j], wd.z, d2);
            }
        }
#pragma unroll
        for (int off = 16; off; off >>= 1) {
            d0 += __shfl_xor_sync(0xffffffffu, d0, off);
            d1 += __shfl_xor_sync(0xffffffffu, d1, off);
            d2 += __shfl_xor_sync(0xffffffffu, d2, off);
        }
        if (lane < 3) {
            float D = (lane == 0 ? d0 : (lane == 1 ? d1 : d2)) + s_bd[lane];
            float s = 1.f / (1.f + expf(-D));
            unsigned bits = __float_as_uint(s);
            unsigned key = bits ^ ((unsigned)((int)bits >> 31) | 0x80000000u);
            g_keys[gw * 3 + lane] = key;
        }
    }
}

// ---------------- 16-bit-bin top-k threshold ----------------
__global__ void zero16_kernel() {
    int i = blockIdx.x * blockDim.x + threadIdx.x;
    if (i < 65536) g_hist16[i] = 0;
    if (i == 0) { g_candCount = 0; g_numKeep = 0; }
}

__global__ void hist16_kernel() {
    for (int i = blockIdx.x * blockDim.x + threadIdx.x; i < NANCH;
         i += gridDim.x * blockDim.x)
        atomicAdd(&g_hist16[g_keys[i] >> 16], 1u);
}

// single block, 1024 threads, register-light: two streaming passes over g_hist16
__global__ void __launch_bounds__(1024) select16_kernel(int K) {
    __shared__ unsigned tot[1024];
    int t = threadIdx.x;
    int b0 = t * 64;
    unsigned sum = 0;
    for (int i = 0; i < 64; i++) sum += g_hist16[b0 + i];
    tot[t] = sum;
    __syncthreads();
    // suffix sum across threads
    for (int d = 1; d < 1024; d <<= 1) {
        unsigned v = (t + d < 1024) ? tot[t + d] : 0u;
        __syncthreads();
        tot[t] += v;
        __syncthreads();
    }
    unsigned suffAfter = (t < 1023) ? tot[t + 1] : 0u;  // keys in bins >= (t+1)*64
    // only the thread whose chunk straddles K walks its bins
    if (tot[t] >= (unsigned)K && suffAfter < (unsigned)K) {
        unsigned run = suffAfter;
        for (int i = 63; i >= 0; i--) {
            unsigned before = run;
            run += g_hist16[b0 + i];
            if (run >= (unsigned)K && before < (unsigned)K) {
                g_prefix = ((unsigned)(b0 + i)) << 16;
                break;
            }
        }
    }
}

// ---------------- pool marking ----------------
__global__ void zero_flags_kernel() {
    int i = blockIdx.x * blockDim.x + threadIdx.x;
    if (i < NPIX) g_pixFlag[i] = 0;
    if (i == 0) g_poolCnt = 0;
}

__global__ void mark_compact_kernel() {
    unsigned T = g_prefix;
    for (int i = blockIdx.x * blockDim.x + threadIdx.x; i < NANCH;
         i += gridDim.x * blockDim.x) {
        if (g_keys[i] >= T) {
            int pix = i / 3;
            if (atomicExch(&g_pixFlag[pix], 1) == 0) {
                int p = atomicAdd(&g_poolCnt, 1);
                if (p < POOLMAX) g_poolPix[p] = pix;
            }
        }
    }
}

// ---------------- exact fp32 recompute of pool pixels (R1-identical chain) ----------------
__global__ void __launch_bounds__(256) exact_conv_kernel(const float* __restrict__ bias) {
    __shared__ float sA[32][33];
    __shared__ float sW[32][264];
    __shared__ int s_pix[32], s_base[32], s_W[32], s_H[32], s_py[32], s_px[32];

    const int tid = threadIdx.x;
    const int cnt = g_poolCnt < POOLMAX ? g_poolCnt : POOLMAX;
    const int ptile = blockIdx.x;
    if (ptile * 32 >= cnt) return;
    const int oc0 = blockIdx.y * 256;

    if (tid < 32) {
        int idx = ptile * 32 + tid;
        int pix = (idx < cnt) ? g_poolPix[idx] : -1;
        s_pix[tid] = pix;
        if (pix >= 0) {
            int l = 0;
            while (l < 4 && pix >= c_pixBase[l + 1]) l++;
            int local = pix - c_pixBase[l];
            int Wl = c_W[l];
            s_base[tid] = c_pixBase[l];
            s_W[tid] = Wl;
            s_H[tid] = c_H[l];
            s_py[tid] = local / Wl;
            s_px[tid] = local - (local / Wl) * Wl;
        }
    }
    __syncthreads();

    const int lane = tid & 31, wid = tid >> 5;
    const int ocL = wid * 32 + (lane >> 3) * 8;
    const int p0 = (lane & 7) * 4;

    const int ap = tid >> 3;
    const int akq = (tid & 7) * 4;
    const int wkk = tid >> 6;
    const int woc = (tid & 63) * 4;

    float acc[4][8];
#pragma unroll
    for (int i = 0; i < 4; i++)
#pragma unroll
        for (int j = 0; j < 8; j++) acc[i][j] = 0.f;

    for (int chunk = 0; chunk < 72; chunk++) {
        const int tap = chunk >> 3;
        const int ic0 = (chunk & 7) * 32;
        const int dy = tap / 3 - 1;
        const int dx = tap - (tap / 3) * 3 - 1;
        const int k0 = chunk * 32;
        {
            float4 val = make_float4(0.f, 0.f, 0.f, 0.f);
            int pix = s_pix[ap];
            if (pix >= 0) {
                int iy = s_py[ap] + dy, ix = s_px[ap] + dx;
                if ((unsigned)iy < (unsigned)s_H[ap] && (unsigned)ix < (unsigned)s_W[ap]) {
                    int np = s_base[ap] + iy * s_W[ap] + ix;
                    val = *(const float4*)(g_fp + (size_t)np * 256 + ic0 + akq);
                }
            }
            sA[ap][akq + 0] = val.x;
            sA[ap][akq + 1] = val.y;
            sA[ap][akq + 2] = val.z;
            sA[ap][akq + 3] = val.w;
        }
#pragma unroll
        for (int r = 0; r < 8; r++) {
            int kk = r * 4 + wkk;
            *(float4*)&sW[kk][woc] =
                *(const float4*)(g_wT + (size_t)(k0 + kk) * 512 + oc0 + woc);
        }
        __syncthreads();
#pragma unroll 8
        for (int kk = 0; kk < 32; kk++) {
            float a0 = sA[p0 + 0][kk];
            float a1 = sA[p0 + 1][kk];
            float a2 = sA[p0 + 2][kk];
            float a3 = sA[p0 + 3][kk];
#pragma unroll
            for (int j = 0; j < 8; j++) {
                float w = sW[kk][ocL + j];
                acc[0][j] = fmaf(a0, w, acc[0][j]);
                acc[1][j] = fmaf(a1, w, acc[1][j]);
                acc[2][j] = fmaf(a2, w, acc[2][j]);
                acc[3][j] = fmaf(a3, w, acc[3][j]);
            }
        }
        __syncthreads();
    }

#pragma unroll
    for (int i = 0; i < 4; i++) {
        int pix = s_pix[p0 + i];
        if (pix >= 0) {
            float* o = g_f + (size_t)pix * 512 + oc0 + ocL;
#pragma unroll
            for (int j = 0; j < 8; j++) o[j] = acc[i][j] + bias[oc0 + ocL + j];
        }
    }
}

// ---------------- exact heads on pool pixels (R1-identical) ----------------
__device__ __forceinline__ void heads_pixel(int gw, int lane,
        const float* __restrict__ sw, const float* __restrict__ sb,
        const float* __restrict__ bw, const float* __restrict__ bb)
{
    const float* f = g_f + (size_t)gw * 512;
    float4 v[4];
#pragma unroll
    for (int j = 0; j < 4; j++)
        v[j] = *(const float4*)(f + j * 128 + lane * 4);

    float c[6];
#pragma unroll
    for (int ch = 0; ch < 6; ch++) {
        const float* w = sw + ch * 512;
        float s = 0.f;
#pragma unroll
        for (int j = 0; j < 4; j++) {
            float4 ww = *(const float4*)(w + j * 128 + lane * 4);
            s += v[j].x * ww.x + v[j].y * ww.y + v[j].z * ww.z + v[j].w * ww.w;
        }
#pragma unroll
        for (int off = 16; off; off >>= 1) s += __shfl_xor_sync(0xffffffffu, s, off);
        c[ch] = s + sb[ch];
    }
    float d[12];
#pragma unroll
    for (int ch = 0; ch < 12; ch++) {
        const float* w = bw + ch * 512;
        float s = 0.f;
#pragma unroll
        for (int j = 0; j < 4; j++) {
            float4 ww = *(const float4*)(w + j * 128 + lane * 4);
            s += v[j].x * ww.x + v[j].y * ww.y + v[j].z * ww.z + v[j].w * ww.w;
        }
#pragma unroll
        for (int off = 16; off; off >>= 1) s += __shfl_xor_sync(0xffffffffu, s, off);
        d[ch] = s + bb[ch];
    }
    int base = gw * 3;
    if (lane < 3) {
        float s = 1.f / (1.f + expf(c[lane] - c[3 + lane]));
        unsigned bits = __float_as_uint(s);
        unsigned key = bits ^ ((unsigned)((int)bits >> 31) | 0x80000000u);
        g_keys[base + lane] = key;
    }
    if (lane < 12) {
        g_deltas[(size_t)base * 4 + lane] = d[lane];
    }
}

__global__ void heads_pool_kernel(const float* __restrict__ sw, const float* __restrict__ sb,
                                  const float* __restrict__ bw, const float* __restrict__ bb)
{
    int i = (blockIdx.x * blockDim.x + threadIdx.x) >> 5;
    int lane = threadIdx.x & 31;
    if (i >= g_poolCnt) return;
    heads_pixel(g_poolPix[i], lane, sw, sb, bw, bb);
}

// ---------------- compact ----------------
__global__ void compact_kernel() {
    unsigned T = g_prefix;
    for (int i = blockIdx.x * blockDim.x + threadIdx.x; i < NANCH;
         i += gridDim.x * blockDim.x) {
        unsigned k = g_keys[i];
        if (k >= T) {
            int p = atomicAdd(&g_candCount, 1);
            if (p < CAND_MAX)
                g_cand[p] = ((unsigned long long)k << 32) | (unsigned)(~i);
        }
    }
}

// ---------------- bitonic sort of candidates (key desc, idx asc) ----------------
__global__ void sort_kernel() {
    extern __shared__ unsigned long long s[];
    int tid = threadIdx.x;
    int cnt = g_candCount;
    if (cnt > CAND_MAX) cnt = CAND_MAX;
    for (int i = tid; i < CAND_MAX; i += blockDim.x)
        s[i] = (i < cnt) ? g_cand[i] : 0ULL;
    __syncthreads();
    for (int k = 2; k <= CAND_MAX; k <<= 1) {
        for (int j = k >> 1; j > 0; j >>= 1) {
            for (int i = tid; i < CAND_MAX; i += blockDim.x) {
                int ixj = i ^ j;
                if (ixj > i) {
                    unsigned long long a = s[i], b = s[ixj];
                    bool desc = ((i & k) == 0);
                    if (desc ? (a < b) : (a > b)) { s[i] = b; s[ixj] = a; }
                }
            }
            __syncthreads();
        }
    }
    for (int i = tid; i < PRE_NMS; i += blockDim.x) {
        unsigned long long e = s[i];
        unsigned idx = ~(unsigned)(e & 0xffffffffu);
        unsigned key = (unsigned)(e >> 32);
        unsigned bits = (key & 0x80000000u) ? (key ^ 0x80000000u) : ~key;
        g_selIdx[i] = (int)idx;
        g_selScore[i] = __uint_as_float(bits);
    }
}

// ---------------- decode + clip only selected 6000 ----------------
__global__ void decode_kernel(const float* __restrict__ im_info) {
    int i = blockIdx.x * blockDim.x + threadIdx.x;
    if (i >= PRE_NMS) return;
    int idx = g_selIdx[i];
    int l = 0;
    while (l < 4 && idx >= c_aoff[l + 1]) l++;
    int local = idx - c_aoff[l];
    int p = local / 3, a = local - p * 3;
    int W = c_W[l];
    int y = p / W, x = p - y * W;
    float stride = (float)c_stride[l];
    float cb = (stride - 1.f) * 0.5f;
    float ws = c_ws0[l * 3 + a] * 8.f, hs = c_hs0[l * 3 + a] * 8.f;
    float sx = x * stride, sy = y * stride;
    float ax1 = sx + cb - 0.5f * (ws - 1.f);
    float ay1 = sy + cb - 0.5f * (hs - 1.f);
    float ax2 = sx + cb + 0.5f * (ws - 1.f);
    float ay2 = sy + cb + 0.5f * (hs - 1.f);
    float w = ax2 - ax1 + 1.f, h = ay2 - ay1 + 1.f;
    float cx = ax1 + 0.5f * w, cy = ay1 + 0.5f * h;
    const float* dd = g_deltas + (size_t)idx * 4;
    float pcx = dd[0] * w + cx;
    float pcy = dd[1] * h + cy;
    float pw = expf(dd[2]) * w;
    float ph = expf(dd[3]) * h;
    float imW = im_info[1] - 1.f, imH = im_info[0] - 1.f;
    g_boxes[i * 4 + 0] = fminf(fmaxf(pcx - 0.5f * pw, 0.f), imW);
    g_boxes[i * 4 + 1] = fminf(fmaxf(pcy - 0.5f * ph, 0.f), imH);
    g_boxes[i * 4 + 2] = fminf(fmaxf(pcx + 0.5f * pw, 0.f), imW);
    g_boxes[i * 4 + 3] = fminf(fmaxf(pcy + 0.5f * ph, 0.f), imH);
}

// ---------------- IoU suppression bitmask (smem-tiled) ----------------
__global__ void iou_kernel() {
    __shared__ float4 sj[64];
    int wb = blockIdx.y;
    int t = threadIdx.x;
    int j0 = wb * 64;
    {
        int j = j0 + t;
        sj[t] = (j < PRE_NMS) ? ((const float4*)g_boxes)[j]
                              : make_float4(0.f, 0.f, 0.f, 0.f);
    }
    __syncthreads();
    int i = blockIdx.x * 64 + t;
    if (i >= PRE_NMS) return;
    float4 bi = ((const float4*)g_boxes)[i];
    float areaI = (bi.z - bi.x + 1.f) * (bi.w - bi.y + 1.f);
    unsigned long long m = 0;
    int jend = PRE_NMS - j0; if (jend > 64) jend = 64;
    for (int jj = 0; jj < jend; jj++) {
        float4 bj = sj[jj];
        float areaJ = (bj.z - bj.x + 1.f) * (bj.w - bj.y + 1.f);
        float iw = fminf(bi.z, bj.z) - fmaxf(bi.x, bj.x) + 1.f;
        float ih = fminf(bi.w, bj.w) - fmaxf(bi.y, bj.y) + 1.f;
        iw = fmaxf(iw, 0.f); ih = fmaxf(ih, 0.f);
        float inter = iw * ih;
        float iou = inter / (areaJ + areaI - inter);
        if (iou > NMS_TH) m |= (1ULL << jj);
    }
    g_iou[(size_t)i * NWORDS + wb] = m;
}

// ---------------- single-warp greedy NMS with 4-way row prefetch ----------------
__global__ void nms_kernel() {
    int lane = threadIdx.x;
    unsigned long long rem0 = 0, rem1 = 0, rem2 = 0;
    int w2 = lane + 64;
    if (w2 == 93) rem2 = ~((1ULL << 48) - 1ULL);
    else if (w2 > 93) rem2 = ~0ULL;
    int nk = 0;
    while (nk < POST_NMS) {
        unsigned long long a0 = ~rem0, a1 = ~rem1, a2 = ~rem2;
        int cand[4] = {-1, -1, -1, -1};
#pragma unroll
        for (int t = 0; t < 4; t++) {
            unsigned b0 = __ballot_sync(0xffffffffu, a0 != 0ULL);
            unsigned b1 = __ballot_sync(0xffffffffu, a1 != 0ULL);
            unsigned b2 = __ballot_sync(0xffffffffu, a2 != 0ULL);
            int slot = -1, src = 0;
            if (b0) { slot = 0; src = __ffs(b0) - 1; }
            else if (b1) { slot = 1; src = __ffs(b1) - 1; }
            else if (b2) { slot = 2; src = __ffs(b2) - 1; }
            if (slot < 0) break;
            unsigned long long mysel = (slot == 0) ? a0 : ((slot == 1) ? a1 : a2);
            int mybit = __ffsll((long long)mysel) - 1;
            int bit = __shfl_sync(0xffffffffu, mybit, src);
            cand[t] = (slot * 32 + src) * 64 + bit;
            if (lane == src) {
                if (slot == 0) a0 &= (a0 - 1);
                else if (slot == 1) a1 &= (a1 - 1);
                else a2 &= (a2 - 1);
            }
        }
        if (cand[0] < 0) break;
        unsigned long long r[4][3];
#pragma unroll
        for (int t = 0; t < 4; t++) {
            if (cand[t] >= 0) {
                const unsigned long long* row = g_iou + (size_t)cand[t] * NWORDS;
                r[t][0] = __ldg(row + lane);
                r[t][1] = __ldg(row + lane + 32);
                r[t][2] = (w2 < NWORDS) ? __ldg(row + w2) : 0ULL;
            } else {
                r[t][0] = r[t][1] = r[t][2] = 0ULL;
            }
        }
#pragma unroll
        for (int t = 0; t < 4; t++) {
            int idx = cand[t];
            if (idx < 0 || nk >= POST_NMS) break;
            if (t > 0) {
                int w = idx >> 6, b = idx & 63;
                unsigned long long mine = (w < 32) ? rem0 : ((w < 64) ? rem1 : rem2);
                unsigned long long ow = __shfl_sync(0xffffffffu, mine, w & 31);
                if ((ow >> b) & 1ULL) continue;
            }
            if (lane == 0) g_keep[nk] = idx;
            nk++;
            rem0 |= r[t][0]; rem1 |= r[t][1]; rem2 |= r[t][2];
        }
    }
    if (lane == 0) g_numKeep = nk;
}

// ---------------- assemble output (1000 x 6) ----------------
__global__ void output_kernel(float* __restrict__ out) {
    int i = blockIdx.x * blockDim.x + threadIdx.x;
    if (i >= POST_NMS) return;
    float x1 = 0, y1 = 0, x2 = 0, y2 = 0, s = 0;
    int nk = g_numKeep;
    if (i < nk) {
        int k = g_keep[i];
        x1 = g_boxes[k * 4 + 0]; y1 = g_boxes[k * 4 + 1];
        x2 = g_boxes[k * 4 + 2]; y2 = g_boxes[k * 4 + 3];
        s = g_selScore[k];
    }
    out[i * 6 + 0] = 0.f;
    out[i * 6 + 1] = x1;
    out[i * 6 + 2] = y1;
    out[i * 6 + 3] = x2;
    out[i * 6 + 4] = y2;
    out[i * 6 + 5] = s;
}

// ---------------- launch ----------------
extern "C" void kernel_launch(void* const* d_in, const int* in_sizes, int n_in,
                              void* d_out, int out_size) {
    const float* feats[5];
    for (int i = 0; i < 5; i++) feats[i] = (const float*)d_in[i];
    const float* im_info = (const float*)d_in[5];
    const float* convW = (const float*)d_in[6];
    const float* convB = (const float*)d_in[7];
    const float* sw = (const float*)d_in[8];
    const float* sb = (const float*)d_in[9];
    const float* bw = (const float*)d_in[10];
    const float* bb = (const float*)d_in[11];
    float* out = (float*)d_out;

    static bool attrDone = false;
    if (!attrDone) {
        cudaFuncSetAttribute(sort_kernel,
                             cudaFuncAttributeMaxDynamicSharedMemorySize, CAND_MAX * 8);
        attrDone = true;
    }

    prep_kernel<<<dim3(1109, 8), dim3(32, 32)>>>(feats[0], feats[1], feats[2],
                                                 feats[3], feats[4]);
    repackw_kernel<<<(512 * 2304 + 255) / 256, 256>>>(convW);
    fold_kernel<<<(2304 * 3 + 255) / 256, 256>>>(sw, sb, convB);
    approx_score_kernel<<<1109, 256>>>();

    // pass 1: approx top-POOL_K threshold (16-bit bins) -> pool pixels
    zero16_kernel<<<64, 1024>>>();
    hist16_kernel<<<416, 256>>>();
    select16_kernel<<<1, 1024>>>(POOL_K);
    zero_flags_kernel<<<(NPIX + 255) / 256, 256>>>();
    mark_compact_kernel<<<416, 256>>>();
    // exact recompute of pool pixels (R1-identical numerics)
    exact_conv_kernel<<<dim3(256, 2), 256>>>(convB);
    heads_pool_kernel<<<POOLMAX * 32 / 256, 256>>>(sw, sb, bw, bb);
    // pass 2: exact top-PRE_NMS
    zero16_kernel<<<64, 1024>>>();
    hist16_kernel<<<416, 256>>>();
    select16_kernel<<<1, 1024>>>(PRE_NMS);
    compact_kernel<<<416, 256>>>();
    sort_kernel<<<1, 1024, CAND_MAX * 8>>>();
    decode_kernel<<<(PRE_NMS + 255) / 256, 256>>>(im_info);
    iou_kernel<<<dim3(94, 94), 64>>>();
    nms_kernel<<<1, 32>>>();
    output_kernel<<<(POST_NMS + 255) / 256, 256>>>(out);
}

// round 12
// speedup vs baseline: 3.3896x; 1.0877x over previous
#include <cuda_runtime.h>
#include <math.h>
#include <stdint.h>

#define NPIX 35464
#define NANCH 106392
#define PRE_NMS 6000
#define POOL_K 6656
#define POOLMAX 8192
#define POST_NMS 1000
#define NMS_TH 0.7f
#define CAND_MAX 8192
#define NWORDS 94    // ceil(6000/64)

// ---------------- device scratch ----------------
__device__ float g_f[(size_t)NPIX * 512];     // exact features (pool pixels only)
__device__ float g_fp[(size_t)NPIX * 256];    // fp32 input, pixel-major
__device__ float g_wT[2304 * 512];            // fp32 conv weights [k][oc]
__device__ float g_wd[2304 * 3];              // folded diff weights [k][a]
__device__ float g_wdB[3];                    // folded diff bias
__device__ unsigned g_keys[NANCH];            // approx, then exact for pool anchors
__device__ unsigned g_keysA[NANCH];           // approx keys (filter copy)
__device__ float g_deltas[(size_t)NANCH * 4];
__device__ unsigned g_hist16[65536];
__device__ unsigned g_prefix;
__device__ int g_candCount;
__device__ unsigned long long g_cand[CAND_MAX];
__device__ int g_pixFlag[NPIX];
__device__ int g_poolPix[POOLMAX];
__device__ int g_poolCnt;
__device__ int g_selIdx[PRE_NMS];
__device__ float g_selScore[PRE_NMS];
__device__ float g_boxes[PRE_NMS * 4];
__device__ unsigned long long g_iou[(size_t)PRE_NMS * NWORDS];
__device__ int g_keep[POST_NMS];
__device__ int g_numKeep;

// constants
__constant__ int c_aoff[6] = {0, 79872, 99840, 104832, 106080, 106392};
__constant__ int c_W[5] = {208, 104, 52, 26, 13};
__constant__ int c_H[5] = {128, 64, 32, 16, 8};
__constant__ int c_stride[5] = {4, 8, 16, 32, 64};
__constant__ int c_pixBase[5] = {0, 26624, 33280, 34944, 35360};
__constant__ int c_ws0[15] = {6,4,3, 11,8,6, 23,16,11, 45,32,23, 91,64,45};
__constant__ int c_hs0[15] = {3,4,6, 6,8,12, 12,16,22, 22,32,46, 46,64,90};

// ---------------- prep (all 5 levels fused): NCHW fp32 -> pixel-major fp32 ----------------
__global__ void prep_kernel(const float* __restrict__ p2, const float* __restrict__ p3,
                            const float* __restrict__ p4, const float* __restrict__ p5,
                            const float* __restrict__ p6) {
    __shared__ float sh[32][33];
    int g0 = blockIdx.x * 32;
    int l = 0;
    while (l < 4 && g0 >= c_pixBase[l + 1]) l++;
    const float* f = (l == 0) ? p2 : (l == 1) ? p3 : (l == 2) ? p4 : (l == 3) ? p5 : p6;
    int HW = c_W[l] * c_H[l];
    int base = c_pixBase[l];
    int ic0 = blockIdx.y * 32;
    int tx = threadIdx.x, ty = threadIdx.y;
    int p = g0 - base + tx;
    sh[ty][tx] = (p < HW) ? f[(size_t)(ic0 + ty) * HW + p] : 0.f;
    __syncthreads();
    int pw = g0 - base + ty;
    if (pw < HW)
        g_fp[(size_t)(base + pw) * 256 + ic0 + tx] = sh[tx][ty];
}

// ---------------- weight transpose: [oc][ic][3][3] -> [k][oc], k=tap*256+ic ----------------
__global__ void repackw_kernel(const float* __restrict__ w) {
    int t = blockIdx.x * blockDim.x + threadIdx.x;
    if (t >= 512 * 2304) return;
    int oc = t / 2304, k = t - oc * 2304;
    int tap = k >> 8, ic = k & 255;
    g_wT[k * 512 + oc] = w[oc * 2304 + ic * 9 + tap];
}

// ---------------- fold score-diff head into conv: wd[k][a] = Weff[k][3+a]-Weff[k][a] ----------------
__global__ void fold_kernel(const float* __restrict__ sw, const float* __restrict__ sb,
                            const float* __restrict__ convB) {
    int t = blockIdx.x * blockDim.x + threadIdx.x;
    if (t < 3) {
        float acc = sb[3 + t] - sb[t];
        for (int oc = 0; oc < 512; oc++)
            acc += (sw[(3 + t) * 512 + oc] - sw[t * 512 + oc]) * convB[oc];
        g_wdB[t] = acc;
    }
    if (t >= 2304 * 3) return;
    int k = t / 3, a = t - k * 3;
    const float4* wr = (const float4*)(g_wT + (size_t)k * 512);
    const float4* s0 = (const float4*)(sw + a * 512);
    const float4* s1 = (const float4*)(sw + (3 + a) * 512);
    float acc = 0.f;
#pragma unroll 4
    for (int q = 0; q < 128; q++) {
        float4 wv = wr[q];
        float4 b0 = s0[q], b1 = s1[q];
        acc += wv.x * (b1.x - b0.x) + wv.y * (b1.y - b0.y)
             + wv.z * (b1.z - b0.z) + wv.w * (b1.w - b0.w);
    }
    g_wd[t] = acc;
}

// ---------------- zero everything once ----------------
__global__ void zeroall_kernel() {
    int i = blockIdx.x * blockDim.x + threadIdx.x;
    if (i < 65536) g_hist16[i] = 0;
    if (i < NPIX) g_pixFlag[i] = 0;
    if (i == 0) { g_candCount = 0; g_numKeep = 0; g_poolCnt = 0; }
}

// ---------------- approx scores + fused histogram ----------------
// swizzled smem layout: addr(k) = k*4 + (k>>3)*4 floats -> conflict-free LDS.128
__global__ void __launch_bounds__(256) approx_score_kernel() {
    __shared__ float s_wd[2304 * 4 + 288 * 4];   // 41472 B
    __shared__ float s_bd[3];
    int tid = threadIdx.x;
    for (int k = tid; k < 2304; k += 256) {
        int base = k * 4 + (k >> 3) * 4;
        s_wd[base + 0] = g_wd[k * 3 + 0];
        s_wd[base + 1] = g_wd[k * 3 + 1];
        s_wd[base + 2] = g_wd[k * 3 + 2];
        s_wd[base + 3] = 0.f;
    }
    if (tid < 3) s_bd[tid] = g_wdB[tid];
    __syncthreads();
    int lane = tid & 31;
    const int ic0 = lane * 8;
    for (int p = 0; p < 4; p++) {
        int gw = blockIdx.x * 32 + (tid >> 5) * 4 + p;
        if (gw >= NPIX) break;
        int l = 0;
        while (l < 4 && gw >= c_pixBase[l + 1]) l++;
        const int Wl = c_W[l], Hl = c_H[l];
        int local = gw - c_pixBase[l];
        int py = local / Wl, px = local - py * Wl;
        float d0 = 0.f, d1 = 0.f, d2 = 0.f;
#pragma unroll
        for (int tap = 0; tap < 9; tap++) {
            int dy = tap / 3 - 1, dx = tap % 3 - 1;
            int iy = py + dy, ix = px + dx;
            if ((unsigned)iy >= (unsigned)Hl || (unsigned)ix >= (unsigned)Wl) continue;
            const float* src = g_fp + ((size_t)(c_pixBase[l] + iy * Wl + ix)) * 256 + ic0;
            float4 v0 = *(const float4*)src;
            float4 v1 = *(const float4*)(src + 4);
            float a[8] = {v0.x, v0.y, v0.z, v0.w, v1.x, v1.y, v1.z, v1.w};
            const float* wp = s_wd + tap * 1152 + lane * 36;
#pragma unroll
            for (int j = 0; j < 8; j++) {
                float4 wd = *(const float4*)(wp + j * 4);
                d0 = fmaf(a[j], wd.x, d0);
                d1 = fmaf(a[j], wd.y, d1);
                d2 = fmaf(a[j], wd.z, d2);
            }
        }
#pragma unroll
        for (int off = 16; off; off >>= 1) {
            d0 += __shfl_xor_sync(0xffffffffu, d0, off);
            d1 += __shfl_xor_sync(0xffffffffu, d1, off);
            d2 += __shfl_xor_sync(0xffffffffu, d2, off);
        }
        if (lane < 3) {
            float D = (lane == 0 ? d0 : (lane == 1 ? d1 : d2)) + s_bd[lane];
            float s = 1.f / (1.f + expf(-D));
            unsigned bits = __float_as_uint(s);
            unsigned key = bits ^ ((unsigned)((int)bits >> 31) | 0x80000000u);
            g_keys[gw * 3 + lane] = key;
            g_keysA[gw * 3 + lane] = key;
            atomicAdd(&g_hist16[key >> 16], 1u);
        }
    }
}

// single block, 1024 threads, register-light: two streaming passes over g_hist16
__global__ void __launch_bounds__(1024) select16_kernel(int K) {
    __shared__ unsigned tot[1024];
    int t = threadIdx.x;
    int b0 = t * 64;
    unsigned sum = 0;
    for (int i = 0; i < 64; i++) sum += g_hist16[b0 + i];
    tot[t] = sum;
    __syncthreads();
    for (int d = 1; d < 1024; d <<= 1) {
        unsigned v = (t + d < 1024) ? tot[t + d] : 0u;
        __syncthreads();
        tot[t] += v;
        __syncthreads();
    }
    unsigned suffAfter = (t < 1023) ? tot[t + 1] : 0u;
    if (tot[t] >= (unsigned)K && suffAfter < (unsigned)K) {
        unsigned run = suffAfter;
        for (int i = 63; i >= 0; i--) {
            unsigned before = run;
            run += g_hist16[b0 + i];
            if (run >= (unsigned)K && before < (unsigned)K) {
                g_prefix = ((unsigned)(b0 + i)) << 16;
                break;
            }
        }
    }
}

// ---------------- pool marking ----------------
__global__ void mark_compact_kernel() {
    unsigned T = g_prefix;
    for (int i = blockIdx.x * blockDim.x + threadIdx.x; i < NANCH;
         i += gridDim.x * blockDim.x) {
        if (g_keysA[i] >= T) {
            int pix = i / 3;
            if (atomicExch(&g_pixFlag[pix], 1) == 0) {
                int p = atomicAdd(&g_poolCnt, 1);
                if (p < POOLMAX) g_poolPix[p] = pix;
            }
        }
    }
}

// ---------------- exact fp32 recompute of pool pixels (R1-identical chain) ----------------
__global__ void __launch_bounds__(256) exact_conv_kernel(const float* __restrict__ bias) {
    __shared__ float sA[32][33];
    __shared__ float sW[32][264];
    __shared__ int s_pix[32], s_base[32], s_W[32], s_H[32], s_py[32], s_px[32];

    const int tid = threadIdx.x;
    const int cnt = g_poolCnt < POOLMAX ? g_poolCnt : POOLMAX;
    const int ptile = blockIdx.x;
    if (ptile * 32 >= cnt) return;
    const int oc0 = blockIdx.y * 256;

    if (tid < 32) {
        int idx = ptile * 32 + tid;
        int pix = (idx < cnt) ? g_poolPix[idx] : -1;
        s_pix[tid] = pix;
        if (pix >= 0) {
            int l = 0;
            while (l < 4 && pix >= c_pixBase[l + 1]) l++;
            int local = pix - c_pixBase[l];
            int Wl = c_W[l];
            s_base[tid] = c_pixBase[l];
            s_W[tid] = Wl;
            s_H[tid] = c_H[l];
            s_py[tid] = local / Wl;
            s_px[tid] = local - (local / Wl) * Wl;
        }
    }
    __syncthreads();

    const int lane = tid & 31, wid = tid >> 5;
    const int ocL = wid * 32 + (lane >> 3) * 8;
    const int p0 = (lane & 7) * 4;

    const int ap = tid >> 3;
    const int akq = (tid & 7) * 4;
    const int wkk = tid >> 6;
    const int woc = (tid & 63) * 4;

    float acc[4][8];
#pragma unroll
    for (int i = 0; i < 4; i++)
#pragma unroll
        for (int j = 0; j < 8; j++) acc[i][j] = 0.f;

    for (int chunk = 0; chunk < 72; chunk++) {
        const int tap = chunk >> 3;
        const int ic0 = (chunk & 7) * 32;
        const int dy = tap / 3 - 1;
        const int dx = tap - (tap / 3) * 3 - 1;
        const int k0 = chunk * 32;
        {
            float4 val = make_float4(0.f, 0.f, 0.f, 0.f);
            int pix = s_pix[ap];
            if (pix >= 0) {
                int iy = s_py[ap] + dy, ix = s_px[ap] + dx;
                if ((unsigned)iy < (unsigned)s_H[ap] && (unsigned)ix < (unsigned)s_W[ap]) {
                    int np = s_base[ap] + iy * s_W[ap] + ix;
                    val = *(const float4*)(g_fp + (size_t)np * 256 + ic0 + akq);
                }
            }
            sA[ap][akq + 0] = val.x;
            sA[ap][akq + 1] = val.y;
            sA[ap][akq + 2] = val.z;
            sA[ap][akq + 3] = val.w;
        }
#pragma unroll
        for (int r = 0; r < 8; r++) {
            int kk = r * 4 + wkk;
            *(float4*)&sW[kk][woc] =
                *(const float4*)(g_wT + (size_t)(k0 + kk) * 512 + oc0 + woc);
        }
        __syncthreads();
#pragma unroll 8
        for (int kk = 0; kk < 32; kk++) {
            float a0 = sA[p0 + 0][kk];
            float a1 = sA[p0 + 1][kk];
            float a2 = sA[p0 + 2][kk];
            float a3 = sA[p0 + 3][kk];
#pragma unroll
            for (int j = 0; j < 8; j++) {
                float w = sW[kk][ocL + j];
                acc[0][j] = fmaf(a0, w, acc[0][j]);
                acc[1][j] = fmaf(a1, w, acc[1][j]);
                acc[2][j] = fmaf(a2, w, acc[2][j]);
                acc[3][j] = fmaf(a3, w, acc[3][j]);
            }
        }
        __syncthreads();
    }

#pragma unroll
    for (int i = 0; i < 4; i++) {
        int pix = s_pix[p0 + i];
        if (pix >= 0) {
            float* o = g_f + (size_t)pix * 512 + oc0 + ocL;
#pragma unroll
            for (int j = 0; j < 8; j++) o[j] = acc[i][j] + bias[oc0 + ocL + j];
        }
    }
}

// ---------------- exact heads on pool pixels (R1-identical, weights staged in smem) ----------------
__device__ __forceinline__ void heads_pixel(int gw, int lane,
        const float* __restrict__ sw, const float* __restrict__ sb,
        const float* __restrict__ bw, const float* __restrict__ bb)
{
    const float* f = g_f + (size_t)gw * 512;
    float4 v[4];
#pragma unroll
    for (int j = 0; j < 4; j++)
        v[j] = *(const float4*)(f + j * 128 + lane * 4);

    float c[6];
#pragma unroll
    for (int ch = 0; ch < 6; ch++) {
        const float* w = sw + ch * 512;
        float s = 0.f;
#pragma unroll
        for (int j = 0; j < 4; j++) {
            float4 ww = *(const float4*)(w + j * 128 + lane * 4);
            s += v[j].x * ww.x + v[j].y * ww.y + v[j].z * ww.z + v[j].w * ww.w;
        }
#pragma unroll
        for (int off = 16; off; off >>= 1) s += __shfl_xor_sync(0xffffffffu, s, off);
        c[ch] = s + sb[ch];
    }
    float d[12];
#pragma unroll
    for (int ch = 0; ch < 12; ch++) {
        const float* w = bw + ch * 512;
        float s = 0.f;
#pragma unroll
        for (int j = 0; j < 4; j++) {
            float4 ww = *(const float4*)(w + j * 128 + lane * 4);
            s += v[j].x * ww.x + v[j].y * ww.y + v[j].z * ww.z + v[j].w * ww.w;
        }
#pragma unroll
        for (int off = 16; off; off >>= 1) s += __shfl_xor_sync(0xffffffffu, s, off);
        d[ch] = s + bb[ch];
    }
    int base = gw * 3;
    if (lane < 3) {
        float s = 1.f / (1.f + expf(c[lane] - c[3 + lane]));
        unsigned bits = __float_as_uint(s);
        unsigned key = bits ^ ((unsigned)((int)bits >> 31) | 0x80000000u);
        g_keys[base + lane] = key;
    }
    if (lane < 12) {
        g_deltas[(size_t)base * 4 + lane] = d[lane];
    }
}

__global__ void __launch_bounds__(256) heads_pool_kernel(
        const float* __restrict__ sw, const float* __restrict__ sb,
        const float* __restrict__ bw, const float* __restrict__ bb)
{
    __shared__ __align__(16) float s_sw[6 * 512];
    __shared__ __align__(16) float s_bw[12 * 512];
    int tid = threadIdx.x;
    for (int i = tid; i < 6 * 512 / 4; i += 256)
        ((float4*)s_sw)[i] = ((const float4*)sw)[i];
    for (int i = tid; i < 12 * 512 / 4; i += 256)
        ((float4*)s_bw)[i] = ((const float4*)bw)[i];
    __syncthreads();
    int lane = tid & 31, wid = tid >> 5;
    int cnt = g_poolCnt < POOLMAX ? g_poolCnt : POOLMAX;
    for (int i = blockIdx.x * 8 + wid; i < cnt; i += gridDim.x * 8)
        heads_pixel(g_poolPix[i], lane, s_sw, sb, s_bw, bb);
}

// ---------------- compact: filter by approx key, payload exact key ----------------
__global__ void compact_kernel() {
    unsigned T = g_prefix;
    for (int i = blockIdx.x * blockDim.x + threadIdx.x; i < NANCH;
         i += gridDim.x * blockDim.x) {
        if (g_keysA[i] >= T) {
            unsigned k = g_keys[i];   // exact (pixel is in pool by construction)
            int p = atomicAdd(&g_candCount, 1);
            if (p < CAND_MAX)
                g_cand[p] = ((unsigned long long)k << 32) | (unsigned)(~i);
        }
    }
}

// ---------------- bitonic sort of candidates (key desc, idx asc) ----------------
__global__ void sort_kernel() {
    extern __shared__ unsigned long long s[];
    int tid = threadIdx.x;
    int cnt = g_candCount;
    if (cnt > CAND_MAX) cnt = CAND_MAX;
    for (int i = tid; i < CAND_MAX; i += blockDim.x)
        s[i] = (i < cnt) ? g_cand[i] : 0ULL;
    __syncthreads();
    for (int k = 2; k <= CAND_MAX; k <<= 1) {
        for (int j = k >> 1; j > 0; j >>= 1) {
            for (int i = tid; i < CAND_MAX; i += blockDim.x) {
                int ixj = i ^ j;
                if (ixj > i) {
                    unsigned long long a = s[i], b = s[ixj];
                    bool desc = ((i & k) == 0);
                    if (desc ? (a < b) : (a > b)) { s[i] = b; s[ixj] = a; }
                }
            }
            __syncthreads();
        }
    }
    for (int i = tid; i < PRE_NMS; i += blockDim.x) {
        unsigned long long e = s[i];
        unsigned idx = ~(unsigned)(e & 0xffffffffu);
        unsigned key = (unsigned)(e >> 32);
        unsigned bits = (key & 0x80000000u) ? (key ^ 0x80000000u) : ~key;
        g_selIdx[i] = (int)idx;
        g_selScore[i] = __uint_as_float(bits);
    }
}

// ---------------- decode + clip only selected 6000 ----------------
__global__ void decode_kernel(const float* __restrict__ im_info) {
    int i = blockIdx.x * blockDim.x + threadIdx.x;
    if (i >= PRE_NMS) return;
    int idx = g_selIdx[i];
    int l = 0;
    while (l < 4 && idx >= c_aoff[l + 1]) l++;
    int local = idx - c_aoff[l];
    int p = local / 3, a = local - p * 3;
    int W = c_W[l];
    int y = p / W, x = p - y * W;
    float stride = (float)c_stride[l];
    float cb = (stride - 1.f) * 0.5f;
    float ws = c_ws0[l * 3 + a] * 8.f, hs = c_hs0[l * 3 + a] * 8.f;
    float sx = x * stride, sy = y * stride;
    float ax1 = sx + cb - 0.5f * (ws - 1.f);
    float ay1 = sy + cb - 0.5f * (hs - 1.f);
    float ax2 = sx + cb + 0.5f * (ws - 1.f);
    float ay2 = sy + cb + 0.5f * (hs - 1.f);
    float w = ax2 - ax1 + 1.f, h = ay2 - ay1 + 1.f;
    float cx = ax1 + 0.5f * w, cy = ay1 + 0.5f * h;
    const float* dd = g_deltas + (size_t)idx * 4;
    float pcx = dd[0] * w + cx;
    float pcy = dd[1] * h + cy;
    float pw = expf(dd[2]) * w;
    float ph = expf(dd[3]) * h;
    float imW = im_info[1] - 1.f, imH = im_info[0] - 1.f;
    g_boxes[i * 4 + 0] = fminf(fmaxf(pcx - 0.5f * pw, 0.f), imW);
    g_boxes[i * 4 + 1] = fminf(fmaxf(pcy - 0.5f * ph, 0.f), imH);
    g_boxes[i * 4 + 2] = fminf(fmaxf(pcx + 0.5f * pw, 0.f), imW);
    g_boxes[i * 4 + 3] = fminf(fmaxf(pcy + 0.5f * ph, 0.f), imH);
}

// ---------------- IoU suppression bitmask (smem-tiled) ----------------
__global__ void iou_kernel() {
    __shared__ float4 sj[64];
    int wb = blockIdx.y;
    int t = threadIdx.x;
    int j0 = wb * 64;
    {
        int j = j0 + t;
        sj[t] = (j < PRE_NMS) ? ((const float4*)g_boxes)[j]
                              : make_float4(0.f, 0.f, 0.f, 0.f);
    }
    __syncthreads();
    int i = blockIdx.x * 64 + t;
    if (i >= PRE_NMS) return;
    float4 bi = ((const float4*)g_boxes)[i];
    float areaI = (bi.z - bi.x + 1.f) * (bi.w - bi.y + 1.f);
    unsigned long long m = 0;
    int jend = PRE_NMS - j0; if (jend > 64) jend = 64;
    for (int jj = 0; jj < jend; jj++) {
        float4 bj = sj[jj];
        float areaJ = (bj.z - bj.x + 1.f) * (bj.w - bj.y + 1.f);
        float iw = fminf(bi.z, bj.z) - fmaxf(bi.x, bj.x) + 1.f;
        float ih = fminf(bi.w, bj.w) - fmaxf(bi.y, bj.y) + 1.f;
        iw = fmaxf(iw, 0.f); ih = fmaxf(ih, 0.f);
        float inter = iw * ih;
        float iou = inter / (areaJ + areaI - inter);
        if (iou > NMS_TH) m |= (1ULL << jj);
    }
    g_iou[(size_t)i * NWORDS + wb] = m;
}

// ---------------- single-warp greedy NMS with 8-way row prefetch ----------------
__global__ void nms_kernel() {
    int lane = threadIdx.x;
    unsigned long long rem0 = 0, rem1 = 0, rem2 = 0;
    int w2 = lane + 64;
    if (w2 == 93) rem2 = ~((1ULL << 48) - 1ULL);
    else if (w2 > 93) rem2 = ~0ULL;
    int nk = 0;
    while (nk < POST_NMS) {
        unsigned long long a0 = ~rem0, a1 = ~rem1, a2 = ~rem2;
        int cand[8];
#pragma unroll
        for (int t = 0; t < 8; t++) cand[t] = -1;
#pragma unroll
        for (int t = 0; t < 8; t++) {
            unsigned b0 = __ballot_sync(0xffffffffu, a0 != 0ULL);
            unsigned b1 = __ballot_sync(0xffffffffu, a1 != 0ULL);
            unsigned b2 = __ballot_sync(0xffffffffu, a2 != 0ULL);
            int slot = -1, src = 0;
            if (b0) { slot = 0; src = __ffs(b0) - 1; }
            else if (b1) { slot = 1; src = __ffs(b1) - 1; }
            else if (b2) { slot = 2; src = __ffs(b2) - 1; }
            if (slot < 0) break;
            unsigned long long mysel = (slot == 0) ? a0 : ((slot == 1) ? a1 : a2);
            int mybit = __ffsll((long long)mysel) - 1;
            int bit = __shfl_sync(0xffffffffu, mybit, src);
            cand[t] = (slot * 32 + src) * 64 + bit;
            if (lane == src) {
                if (slot == 0) a0 &= (a0 - 1);
                else if (slot == 1) a1 &= (a1 - 1);
                else a2 &= (a2 - 1);
            }
        }
        if (cand[0] < 0) break;
        unsigned long long r[8][3];
#pragma unroll
        for (int t = 0; t < 8; t++) {
            if (cand[t] >= 0) {
                const unsigned long long* row = g_iou + (size_t)cand[t] * NWORDS;
                r[t][0] = __ldg(row + lane);
                r[t][1] = __ldg(row + lane + 32);
                r[t][2] = (w2 < NWORDS) ? __ldg(row + w2) : 0ULL;
            } else {
                r[t][0] = r[t][1] = r[t][2] = 0ULL;
            }
        }
#pragma unroll
        for (int t = 0; t < 8; t++) {
            int idx = cand[t];
            if (idx < 0 || nk >= POST_NMS) break;
            if (t > 0) {
                int w = idx >> 6, b = idx & 63;
                unsigned long long mine = (w < 32) ? rem0 : ((w < 64) ? rem1 : rem2);
                unsigned long long ow = __shfl_sync(0xffffffffu, mine, w & 31);
                if ((ow >> b) & 1ULL) continue;
            }
            if (lane == 0) g_keep[nk] = idx;
            nk++;
            rem0 |= r[t][0]; rem1 |= r[t][1]; rem2 |= r[t][2];
        }
    }
    if (lane == 0) g_numKeep = nk;
}

// ---------------- assemble output (1000 x 6) ----------------
__global__ void output_kernel(float* __restrict__ out) {
    int i = blockIdx.x * blockDim.x + threadIdx.x;
    if (i >= POST_NMS) return;
    float x1 = 0, y1 = 0, x2 = 0, y2 = 0, s = 0;
    int nk = g_numKeep;
    if (i < nk) {
        int k = g_keep[i];
        x1 = g_boxes[k * 4 + 0]; y1 = g_boxes[k * 4 + 1];
        x2 = g_boxes[k * 4 + 2]; y2 = g_boxes[k * 4 + 3];
        s = g_selScore[k];
    }
    out[i * 6 + 0] = 0.f;
    out[i * 6 + 1] = x1;
    out[i * 6 + 2] = y1;
    out[i * 6 + 3] = x2;
    out[i * 6 + 4] = y2;
    out[i * 6 + 5] = s;
}

// ---------------- launch ----------------
extern "C" void kernel_launch(void* const* d_in, const int* in_sizes, int n_in,
                              void* d_out, int out_size) {
    const float* feats[5];
    for (int i = 0; i < 5; i++) feats[i] = (const float*)d_in[i];
    const float* im_info = (const float*)d_in[5];
    const float* convW = (const float*)d_in[6];
    const float* convB = (const float*)d_in[7];
    const float* sw = (const float*)d_in[8];
    const float* sb = (const float*)d_in[9];
    const float* bw = (const float*)d_in[10];
    const float* bb = (const float*)d_in[11];
    float* out = (float*)d_out;

    static bool attrDone = false;
    if (!attrDone) {
        cudaFuncSetAttribute(sort_kernel,
                             cudaFuncAttributeMaxDynamicSharedMemorySize, CAND_MAX * 8);
        attrDone = true;
    }

    prep_kernel<<<dim3(1109, 8), dim3(32, 32)>>>(feats[0], feats[1], feats[2],
                                                 feats[3], feats[4]);
    repackw_kernel<<<(512 * 2304 + 255) / 256, 256>>>(convW);
    fold_kernel<<<(2304 * 3 + 255) / 256, 256>>>(sw, sb, convB);
    zeroall_kernel<<<(65536 + 255) / 256, 256>>>();
    approx_score_kernel<<<1109, 256>>>();
    select16_kernel<<<1, 1024>>>(POOL_K);
    mark_compact_kernel<<<416, 256>>>();
    exact_conv_kernel<<<dim3(256, 2), 256>>>(convB);
    heads_pool_kernel<<<128, 256>>>(sw, sb, bw, bb);
    compact_kernel<<<416, 256>>>();
    sort_kernel<<<1, 1024, CAND_MAX * 8>>>();
    decode_kernel<<<(PRE_NMS + 255) / 256, 256>>>(im_info);
    iou_kernel<<<dim3(94, 94), 64>>>();
    nms_kernel<<<1, 32>>>();
    output_kernel<<<(POST_NMS + 255) / 256, 256>>>(out);
}